// round 12
// baseline (speedup 1.0000x reference)
#include <cuda_runtime.h>
#include <math.h>

#define NBATCH 2048
#define ALPHA 1e-4f
#define LN_EPS 1e-5f
#define NCHUNK 8
#define CHUNK (NBATCH/NCHUNK)

#define XR_ELEMS (NBATCH*62*64)      /* 8126464 */
#define S_BASE   (XR_ELEMS + 2)

// Scratch: per-batch cheb accumulators [b][tv][16] (kf-contig, padded), transposed tw.
__device__ float g_acc[NBATCH*2976];
__device__ float g_twt[12288];           // [t*64+c][o]

__device__ __forceinline__ float fsig(float x){ return __fdividef(1.0f, 1.0f+__expf(-x)); }

__global__ void prep_kernel(const float* __restrict__ gtw, float* __restrict__ out) {
    int i = blockIdx.x*256 + threadIdx.x;
    if (i < 12288) {
        int o = i/192, c = (i%192)/3, t = i%3;
        g_twt[(t*64+c)*64+o] = gtw[i];
    }
    if (i < 2) out[XR_ELEMS + i] = 0.0f;
}

// ============ KERNEL A: phases 0-4a, 256 threads, 1 batch/block ============
__global__ void __launch_bounds__(256,5) stgcn_a(
    const float* __restrict__ gx, const float* __restrict__ gU1,
    const float* __restrict__ gU2, const float* __restrict__ gU3,
    const float* __restrict__ gbe, const float* __restrict__ gVe,
    const float* __restrict__ gW1, const float* __restrict__ gW2,
    const float* __restrict__ gW3, const float* __restrict__ gbs,
    const float* __restrict__ gVs, const float* __restrict__ ga,
    int b0, float* __restrict__ out)
{
    extern __shared__ float smarr[];
    const int lt = threadIdx.x;
    const int b  = b0 + blockIdx.x;

    float* sx    = smarr;            // 932
    float* sxT   = sx   + 932;       // 932
    float* bufA  = sxT  + 932;       // 3968
    float* bufAt = bufA + 3968;      // 3844
    float* y_s   = bufAt+ 3844;      // 16
    float* lhs_s = y_s  + 16;        // 188
    float* rhs_s = lhs_s+ 188;       // 188
    float* prod_s= rhs_s+ 188;       // 12
    float* E_s   = prod_s+12;        // 12
    float* At_s  = E_s  + 12;        // 12
    float* slhs_s= At_s + 12;        // 188
    float* srhs_s= slhs_s+188;       // 188
    float* colsum= srhs_s+188;       // 64
    float* DgS_s = colsum+ 64;       // 64
    float* d2s_s = DgS_s + 64;       // 64
    float* red_s = d2s_s + 64;       // 8
    float* U2_s  = red_s + 8;        // 312
    float* U1_s  = U2_s + 312;       // 64
    float* U3_s  = U1_s + 64;        // 8
    float* be_s  = U3_s + 8;         // 12
    float* Ve_s  = be_s + 12;        // 12
    float* W1_s  = Ve_s + 12;        // 4
    float* W2_s  = W1_s + 4;         // 16
    float* W3_s  = W2_s + 16;        // 8
    float* a_s   = W3_s + 8;         // 8

    for (int i = lt; i < 930; i += 256) sx[i] = gx[(size_t)b*930 + i];
    if (lt >= 128 && lt < 128+155) {
        U2_s[(lt-128)*2]   = gU2[(lt-128)*2];
        U2_s[(lt-128)*2+1] = gU2[(lt-128)*2+1];
    }
    if (lt < 62) U1_s[lt] = gU1[lt];
    else if (lt >= 64 && lt < 69)  U3_s[lt-64] = gU3[lt-64];
    else if (lt >= 70 && lt < 79)  be_s[lt-70] = gbe[lt-70];
    else if (lt >= 80 && lt < 89)  Ve_s[lt-80] = gVe[lt-80];
    else if (lt >= 90 && lt < 93)  W1_s[lt-90] = gW1[lt-90];
    else if (lt >= 96 && lt < 111) W2_s[lt-96] = gW2[lt-96];
    else if (lt >= 112 && lt < 117) W3_s[lt-112] = gW3[lt-112];
    else if (lt >= 118 && lt < 123) a_s[lt-118] = ga[lt-118];
    __syncthreads();

    // P1: y + rhs
    if (lt < 15) {
        int t = lt/5, f = lt%5;
        float s = 0.f;
        for (int v = 0; v < 62; v++) s += sx[t*310+v*5+f]*U1_s[v];
        y_s[t*5+f] = s;
    }
    if (lt >= 32 && lt < 218) {
        int r = lt-32;
        int v = r/3, t = r%3;
        const float* xr = sx + t*310 + v*5;
        float s = 0.f;
        #pragma unroll
        for (int f=0; f<5; f++) s += U3_s[f]*xr[f];
        rhs_s[v*3+t] = s;
    }
    __syncthreads();
    // P2: lhs
    if (lt < 186) {
        int t = lt/62, u = lt%62;
        float s = 0.f;
        #pragma unroll
        for (int f=0; f<5; f++) s += y_s[t*5+f]*U2_s[f*62+u];
        lhs_s[t*62+u] = s;
    }
    __syncthreads();
    // P3: prod
    if (lt < 9) {
        int t = lt/3, u = lt%3;
        float s = 0.f;
        for (int v=0; v<62; v++) s += lhs_s[t*62+v]*rhs_s[v*3+u];
        prod_s[t*3+u] = s;
    }
    __syncthreads();
    // P4: E
    if (lt < 9) {
        int t = lt/3, u = lt%3;
        float s = 0.f;
        #pragma unroll
        for (int k=0; k<3; k++) s += Ve_s[t*3+k]*fsig(prod_s[k*3+u]+be_s[k*3+u]);
        E_s[t*3+u] = s;
    }
    __syncthreads();
    // P5: softmax over t
    if (lt < 3) {
        int u = lt;
        float m = fmaxf(E_s[u], fmaxf(E_s[3+u], E_s[6+u]));
        float e0=__expf(E_s[u]-m), e1=__expf(E_s[3+u]-m), e2=__expf(E_s[6+u]-m);
        float inv = __fdividef(1.0f, e0+e1+e2);
        At_s[u]=e0*inv; At_s[3+u]=e1*inv; At_s[6+u]=e2*inv;
    }
    __syncthreads();
    // P6: x_TAt
    for (int i = lt; i < 930; i += 256) {
        int u = i/310, r = i%310;
        sxT[i] = (sx[r]*At_s[u] + sx[310+r]*At_s[3+u] + sx[620+r]*At_s[6+u]) * 0.056796183f;
    }
    __syncthreads();
    // P7: slhs + srhs
    if (lt < 186) {
        int v = lt/3, s = lt%3;
        float acc = 0.f;
        #pragma unroll
        for (int f=0; f<5; f++) {
            float yv = sxT[v*5+f]*W1_s[0] + sxT[310+v*5+f]*W1_s[1] + sxT[620+v*5+f]*W1_s[2];
            acc += yv*W2_s[f*3+s];
        }
        slhs_s[v*3+s] = acc;
        int t = lt/62, vv = lt%62;
        const float* xr = sxT + t*310 + vv*5;
        float s2 = 0.f;
        #pragma unroll
        for (int f=0; f<5; f++) s2 += W3_s[f]*xr[f];
        srhs_s[t*62+vv] = s2;
    }
    __syncthreads();
    // P8: sigmoid map [w][v] stride 64
    for (int i = lt; i < 3844; i += 256) {
        int w = i/62, v = i%62;
        float p = slhs_s[w*3]*srhs_s[v] + slhs_s[w*3+1]*srhs_s[62+v]
                + slhs_s[w*3+2]*srhs_s[124+v] + gbs[i];
        bufA[w*64+v] = fsig(p);
    }
    if (lt < 62) { bufA[lt*64+62]=0.f; bufA[lt*64+63]=0.f; }
    __syncthreads();
    // P9: Sm matmul (2u x 8v tile), Vs via L1
    {
        int u2 = lt>>3;
        int vq = lt&7;
        int u0 = u2*2;
        if (u0 < 62) {
            float acc[16];
            #pragma unroll
            for (int k=0;k<16;k++) acc[k]=0.f;
            const float* va_p = gVs + u0*62;
            const float* vb_p = va_p + 62;
            for (int w=0; w<62; w++) {
                float va = __ldg(va_p + w);
                float vb = __ldg(vb_p + w);
                const float4* rowp = reinterpret_cast<const float4*>(bufA + w*64 + vq*8);
                float4 s0 = rowp[0], s1 = rowp[1];
                float sv[8] = {s0.x,s0.y,s0.z,s0.w,s1.x,s1.y,s1.z,s1.w};
                #pragma unroll
                for (int j=0;j<8;j++) { acc[j] += va*sv[j]; acc[8+j] += vb*sv[j]; }
            }
            #pragma unroll
            for (int j=0;j<8;j++) {
                int v = vq*8+j;
                if (v < 62) {
                    bufAt[u0*62+v]     = acc[j];
                    bufAt[(u0+1)*62+v] = acc[8+j];
                }
            }
        }
    }
    __syncthreads();
    // P10: softmax over u per column v (4 lanes/col)
    {
        int v = lt>>2, g = lt&3;
        bool act = (v < 62);
        float m = -1e30f;
        if (act) for (int u=g; u<62; u+=4) m = fmaxf(m, bufAt[u*62+v]);
        m = fmaxf(m, __shfl_xor_sync(0xffffffffu, m, 1));
        m = fmaxf(m, __shfl_xor_sync(0xffffffffu, m, 2));
        float ssum = 0.f;
        if (act) for (int u=g; u<62; u+=4) { float e = __expf(bufAt[u*62+v]-m); bufAt[u*62+v]=e; ssum+=e; }
        ssum += __shfl_xor_sync(0xffffffffu, ssum, 1);
        ssum += __shfl_xor_sync(0xffffffffu, ssum, 2);
        float inv = __fdividef(1.0f, ssum);
        if (act) for (int u=g; u<62; u+=4) bufAt[u*62+v] *= inv;
    }
    __syncthreads();
    // P11: tmpS (reuse bufA, stride 62)
    const float* xm = sx + 310;
    {
        float a0=a_s[0],a1=a_s[1],a2=a_s[2],a3=a_s[3],a4=a_s[4];
        for (int i = lt; i < 3844; i += 256) {
            int ii = i/62, jj = i%62;
            const float* xi = xm + ii*5; const float* xj = xm + jj*5;
            float e = fabsf(xi[0]-xj[0])*a0 + fabsf(xi[1]-xj[1])*a1 + fabsf(xi[2]-xj[2])*a2
                    + fabsf(xi[3]-xj[3])*a3 + fabsf(xi[4]-xj[4])*a4;
            bufA[i] = __expf(fmaxf(e, 0.0f));
        }
    }
    __syncthreads();
    // P12: column reciprocal
    {
        int j = lt>>2, g = lt&3;
        bool act = (j < 62);
        float cs = 0.f;
        if (act) for (int i=g; i<62; i+=4) cs += bufA[i*62+j];
        cs += __shfl_xor_sync(0xffffffffu, cs, 1);
        cs += __shfl_xor_sync(0xffffffffu, cs, 2);
        if (act && g==0) colsum[j] = __fdividef(1.0f, cs);
    }
    __syncthreads();
    // P13: normalize + store S
    for (int i = lt; i < 3844; i += 256) {
        float s = bufA[i] * colsum[i%62];
        bufA[i] = s;
        out[S_BASE + (size_t)b*3844 + i] = s;
    }
    __syncthreads();
    // P14: Dg + d2
    {
        int j = lt>>2, g = lt&3;
        bool act = (j < 62);
        float cs = 0.f, dd = 0.f;
        if (act) {
            const float* xj = xm + j*5;
            for (int i=g; i<62; i+=4) {
                cs += bufA[i*62+j];
                const float* xi = xm + i*5;
                #pragma unroll
                for (int f=0; f<5; f++) { float d = xj[f]-xi[f]; dd += d*d; }
            }
        }
        cs += __shfl_xor_sync(0xffffffffu, cs, 1);
        cs += __shfl_xor_sync(0xffffffffu, cs, 2);
        dd += __shfl_xor_sync(0xffffffffu, dd, 1);
        dd += __shfl_xor_sync(0xffffffffu, dd, 2);
        if (act && g==0) { DgS_s[j] = cs; d2s_s[j] = dd; }
    }
    __syncthreads();
    // P15: Sloss partials
    {
        float sl = 0.f;
        for (int i = lt; i < 3844; i += 256) sl += bufA[i]*bufA[i];
        #pragma unroll
        for (int o=16; o; o>>=1) sl += __shfl_xor_sync(0xffffffffu, sl, o);
        if ((lt&31)==0) red_s[lt>>5] = sl;
    }
    __syncthreads();
    // P16: cheb accumulators -> g_acc [b][tv][16] + loss finalize
    if (lt < 186) {
        int t = lt/62, v = lt%62;
        float acc[15];
        #pragma unroll
        for (int k=0;k<15;k++) acc[k]=0.f;
        float dgm1 = DgS_s[v] - 1.0f;
        for (int u=0; u<62; u++) {
            float s  = bufA[u*62+v];
            float at = bufAt[u*62+v];
            float delta = (u==v) ? 1.0f : 0.0f;
            float lt_ = dgm1*delta - s;
            float c2 = 2.0f*lt_*lt_ - delta;
            float t0 = delta*at, t1 = lt_*at, t2 = c2*at;
            const float* xr = sx + t*310 + u*5;
            #pragma unroll
            for (int f=0; f<5; f++) {
                float xv = xr[f];
                acc[f]    += t0*xv;
                acc[5+f]  += t1*xv;
                acc[10+f] += t2*xv;
            }
        }
        float4* gp = reinterpret_cast<float4*>(g_acc + (size_t)b*2976 + (size_t)(t*62+v)*16);
        gp[0] = make_float4(acc[0],acc[1],acc[2],acc[3]);
        gp[1] = make_float4(acc[4],acc[5],acc[6],acc[7]);
        gp[2] = make_float4(acc[8],acc[9],acc[10],acc[11]);
        gp[3] = make_float4(acc[12],acc[13],acc[14],0.0f);
    } else if (lt == 192) {
        float sl = 0.f;
        #pragma unroll
        for (int w=0; w<8; w++) sl += red_s[w];
        atomicAdd(out + XR_ELEMS, sl * (ALPHA/(float)NBATCH));
        float dp = 0.f;
        for (int j=0; j<62; j++) dp += DgS_s[j]*d2s_s[j];
        atomicAdd(out + XR_ELEMS + 1, dp * ALPHA);
    }
}

// ============ K3: phases 4b-6 ============
__global__ void __launch_bounds__(512,3) stgcn_k3(
    const float* __restrict__ gx, const float* __restrict__ gTheta,
    const float* __restrict__ gtb, const float* __restrict__ grw,
    const float* __restrict__ grb, const float* __restrict__ ggamma,
    const float* __restrict__ gbeta, int b0, float* __restrict__ out)
{
    extern __shared__ float smarr[];
    const int tid = threadIdx.x;
    const int b = b0 + blockIdx.x;

    float* sg    = smarr;              // 12288 [t][c][v] rowstride 64
    float* zb    = sg   + 12288;       // 4032  z [v][o] rowstride 65
    float* Th_s  = zb   + 4032;        // 960   [kf][o]
    float* x0_s  = Th_s + 960;         // 320
    float* tb_s  = x0_s + 320;         // 64
    float* rb_s  = tb_s + 64;          // 64
    float* rw_s  = rb_s + 64;          // 320
    float* gam_s = rw_s + 320;         // 64
    float* bet_s = gam_s+ 64;          // 64
    float* mu_s  = bet_s+ 64;          // 64
    float* iv_s  = mu_s + 64;          // 64

    for (int i = tid; i < 960; i += 512) Th_s[i] = gTheta[i];
    for (int i = tid; i < 310; i += 512) x0_s[i] = gx[(size_t)b*930 + i];
    for (int i = tid; i < 320; i += 512) rw_s[i] = grw[i];
    if (tid < 64) { tb_s[tid]=gtb[tid]; rb_s[tid]=grb[tid]; gam_s[tid]=ggamma[tid]; bet_s[tid]=gbeta[tid]; }
    __syncthreads();

    // Phase 4b: Theta contraction -> sg (float4 Th loads)
    if (tid < 372) {
        int oh = (tid >= 186);
        int r = tid - oh*186;
        int t = r/62, v = r%62;
        int tv = t*62+v;
        const float4* ap4 = reinterpret_cast<const float4*>(g_acc + (size_t)b*2976 + (size_t)tv*16);
        float4 A0=__ldg(ap4), A1=__ldg(ap4+1), A2=__ldg(ap4+2), A3=__ldg(ap4+3);
        float a0[15] = {A0.x,A0.y,A0.z,A0.w, A1.x,A1.y,A1.z,A1.w,
                        A2.x,A2.y,A2.z,A2.w, A3.x,A3.y,A3.z};
        const float4* Th4 = reinterpret_cast<const float4*>(Th_s);  // [kf][16]
        int qb = oh*8;
        float* sgr = sg + t*4096 + v;
        #pragma unroll 2
        for (int q=0; q<8; q++) {
            int oq = qb+q;
            float zx=0.f, zy=0.f, zz=0.f, zw=0.f;
            #pragma unroll
            for (int kf=0; kf<15; kf++) {
                float4 th = Th4[kf*16+oq];
                float av = a0[kf];
                zx += av*th.x; zy += av*th.y; zz += av*th.z; zw += av*th.w;
            }
            int o0 = oq*4;
            sgr[(o0  )*64] = fmaxf(zx, 0.0f);
            sgr[(o0+1)*64] = fmaxf(zy, 0.0f);
            sgr[(o0+2)*64] = fmaxf(zz, 0.0f);
            sgr[(o0+3)*64] = fmaxf(zw, 0.0f);
        }
    }
    for (int i = tid; i < 192; i += 512) {
        int t = i/64, c = i%64;
        sg[t*4096 + c*64 + 62] = 0.f;
        sg[t*4096 + c*64 + 63] = 0.f;
    }
    __syncthreads();

    // Phase 5: temporal conv — 8o x 2v per thread, 2-way k-split, tw via L1
    {
        int og  = tid & 7;            // o-group: o = og*8..+8
        int kh  = (tid >> 3) & 1;     // k-half
        int vg  = tid >> 4;           // 0..31
        int o0  = og*8;
        int v0  = vg*2;
        float acc[16];                // [vj*8+oi]
        #pragma unroll
        for (int k=0;k<16;k++) acc[k]=0.f;
        int tc0 = kh*96;
        #pragma unroll 2
        for (int tc = tc0; tc < tc0+96; tc++) {
            int t = tc>>6, c = tc&63;
            float2 sv = *reinterpret_cast<const float2*>(sg + t*4096 + c*64 + v0);
            const float4* twp = reinterpret_cast<const float4*>(g_twt + (t<<12) + (c<<6) + o0);
            float4 w0 = __ldg(twp), w1 = __ldg(twp+1);
            acc[0]  += sv.x*w0.x; acc[1]  += sv.x*w0.y; acc[2]  += sv.x*w0.z; acc[3]  += sv.x*w0.w;
            acc[4]  += sv.x*w1.x; acc[5]  += sv.x*w1.y; acc[6]  += sv.x*w1.z; acc[7]  += sv.x*w1.w;
            acc[8]  += sv.y*w0.x; acc[9]  += sv.y*w0.y; acc[10] += sv.y*w0.z; acc[11] += sv.y*w0.w;
            acc[12] += sv.y*w1.x; acc[13] += sv.y*w1.y; acc[14] += sv.y*w1.z; acc[15] += sv.y*w1.w;
        }
        #pragma unroll
        for (int k=0;k<16;k++) acc[k] += __shfl_xor_sync(0xffffffffu, acc[k], 8);
        if (kh == 0 && v0 < 62) {
            #pragma unroll
            for (int vj=0; vj<2; vj++) {
                int v = v0+vj;
                if (v < 62) {
                    const float* x0 = x0_s + v*5;
                    float xa=x0[0], xb=x0[1], xc=x0[2], xd=x0[3], xe=x0[4];
                    #pragma unroll
                    for (int oi=0; oi<8; oi++) {
                        int o = o0+oi;
                        float tcv = (acc[vj*8+oi] + tb_s[o]) * 0.25819889f;
                        const float* rwp = rw_s + o*5;
                        float resv = rb_s[o] + xa*rwp[0]+xb*rwp[1]+xc*rwp[2]+xd*rwp[3]+xe*rwp[4];
                        zb[v*65+o] = fmaxf(resv + tcv, 0.0f);
                    }
                }
            }
        }
    }
    __syncthreads();

    // Phase 6: LayerNorm + writeback
    {
        int v = tid>>3, g = tid&7;
        bool act = (v < 62);
        float s = 0.f;
        if (act) for (int o=g; o<64; o+=8) s += zb[v*65+o];
        #pragma unroll
        for (int o=4; o; o>>=1) s += __shfl_xor_sync(0xffffffffu, s, o);
        float mu = s * (1.0f/64.0f);
        float vv = 0.f;
        if (act) for (int o=g; o<64; o+=8) { float d = zb[v*65+o]-mu; vv += d*d; }
        #pragma unroll
        for (int o=4; o; o>>=1) vv += __shfl_xor_sync(0xffffffffu, vv, o);
        vv *= (1.0f/64.0f);
        if (act && g==0) { mu_s[v] = mu; iv_s[v] = rsqrtf(vv + LN_EPS); }
    }
    __syncthreads();
    for (int i = tid; i < 3968; i += 512) {
        int v = i>>6, o = i&63;
        float val = (zb[v*65+o]-mu_s[v])*iv_s[v]*gam_s[o] + bet_s[o];
        out[(size_t)b*3968 + i] = val;
    }
}

#define SMEM_A_BYTES (11124*4)
#define SMEM_K3_BYTES (18304*4)

extern "C" void kernel_launch(void* const* d_in, const int* in_sizes, int n_in,
                              void* d_out, int out_size) {
    const float* x     = (const float*)d_in[0];
    const float* U1    = (const float*)d_in[1];
    const float* U2    = (const float*)d_in[2];
    const float* U3    = (const float*)d_in[3];
    const float* be    = (const float*)d_in[4];
    const float* Ve    = (const float*)d_in[5];
    const float* W1    = (const float*)d_in[6];
    const float* W2    = (const float*)d_in[7];
    const float* W3    = (const float*)d_in[8];
    const float* bs    = (const float*)d_in[9];
    const float* Vs    = (const float*)d_in[10];
    const float* a     = (const float*)d_in[11];
    const float* Theta = (const float*)d_in[12];
    const float* tw    = (const float*)d_in[13];
    const float* tb    = (const float*)d_in[14];
    const float* rw    = (const float*)d_in[15];
    const float* rb    = (const float*)d_in[16];
    const float* gamma = (const float*)d_in[17];
    const float* beta  = (const float*)d_in[18];
    float* out = (float*)d_out;

    static cudaStream_t s2 = 0;
    static cudaEvent_t evA[NCHUNK];
    static cudaEvent_t evDone = 0;
    if (s2 == 0) {
        cudaStreamCreateWithFlags(&s2, cudaStreamNonBlocking);
        for (int i = 0; i < NCHUNK; i++)
            cudaEventCreateWithFlags(&evA[i], cudaEventDisableTiming);
        cudaEventCreateWithFlags(&evDone, cudaEventDisableTiming);
        cudaFuncSetAttribute(stgcn_a,  cudaFuncAttributeMaxDynamicSharedMemorySize, SMEM_A_BYTES);
        cudaFuncSetAttribute(stgcn_k3, cudaFuncAttributeMaxDynamicSharedMemorySize, SMEM_K3_BYTES);
    }

    prep_kernel<<<48, 256>>>(tw, out);
    for (int i = 0; i < NCHUNK; i++) {
        stgcn_a<<<CHUNK, 256, SMEM_A_BYTES>>>(x, U1, U2, U3, be, Ve, W1, W2, W3,
                                              bs, Vs, a, i*CHUNK, out);
        cudaEventRecord(evA[i], 0);
        cudaStreamWaitEvent(s2, evA[i], 0);
        stgcn_k3<<<CHUNK, 512, SMEM_K3_BYTES, s2>>>(x, Theta, tb, rw, rb, gamma, beta,
                                                    i*CHUNK, out);
    }
    cudaEventRecord(evDone, s2);
    cudaStreamWaitEvent(0, evDone, 0);
}

// round 13
// speedup vs baseline: 1.3754x; 1.3754x over previous
#include <cuda_runtime.h>
#include <math.h>

#define NBATCH 2048
#define ALPHA 1e-4f
#define LN_EPS 1e-5f

#define XR_ELEMS (NBATCH*62*64)      /* 8126464 */
#define S_BASE   (XR_ELEMS + 2)

// Scratch: per-batch cheb accumulators [b][tv][16] (kf-contig, padded), transposed tw.
__device__ float g_acc[NBATCH*2976];
__device__ float g_twt[12288];           // [t*64+c][o]

__device__ __forceinline__ float fsig(float x){ return __fdividef(1.0f, 1.0f+__expf(-x)); }

__global__ void prep_kernel(const float* __restrict__ gtw, float* __restrict__ out) {
    int i = blockIdx.x*256 + threadIdx.x;
    if (i < 12288) {
        int o = i/192, c = (i%192)/3, t = i%3;
        g_twt[(t*64+c)*64+o] = gtw[i];
    }
    if (i < 2) out[XR_ELEMS + i] = 0.0f;
}

// ============ KERNEL A: phases 0-4a, 256 threads, 1 batch/block ============
__global__ void __launch_bounds__(256,5) stgcn_a(
    const float* __restrict__ gx, const float* __restrict__ gU1,
    const float* __restrict__ gU2, const float* __restrict__ gU3,
    const float* __restrict__ gbe, const float* __restrict__ gVe,
    const float* __restrict__ gW1, const float* __restrict__ gW2,
    const float* __restrict__ gW3, const float* __restrict__ gbs,
    const float* __restrict__ gVs, const float* __restrict__ ga,
    float* __restrict__ out)
{
    extern __shared__ float smarr[];
    const int lt = threadIdx.x;
    const int b  = blockIdx.x;

    float* sx    = smarr;            // 932
    float* sxT   = sx   + 932;       // 932
    float* bufA  = sxT  + 932;       // 3968
    float* bufAt = bufA + 3968;      // 3844
    float* y_s   = bufAt+ 3844;      // 16
    float* lhs_s = y_s  + 16;        // 188
    float* rhs_s = lhs_s+ 188;       // 188
    float* prod_s= rhs_s+ 188;       // 12
    float* E_s   = prod_s+12;        // 12
    float* At_s  = E_s  + 12;        // 12
    float* slhs_s= At_s + 12;        // 188
    float* srhs_s= slhs_s+188;       // 188
    float* colsum= srhs_s+188;       // 64
    float* DgS_s = colsum+ 64;       // 64
    float* d2s_s = DgS_s + 64;       // 64
    float* red_s = d2s_s + 64;       // 8
    float* U2_s  = red_s + 8;        // 312
    float* U1_s  = U2_s + 312;       // 64
    float* U3_s  = U1_s + 64;        // 8
    float* be_s  = U3_s + 8;         // 12
    float* Ve_s  = be_s + 12;        // 12
    float* W1_s  = Ve_s + 12;        // 4
    float* W2_s  = W1_s + 4;         // 16
    float* W3_s  = W2_s + 16;        // 8
    float* a_s   = W3_s + 8;         // 8

    for (int i = lt; i < 930; i += 256) sx[i] = gx[(size_t)b*930 + i];
    if (lt >= 128 && lt < 128+155) {
        U2_s[(lt-128)*2]   = gU2[(lt-128)*2];
        U2_s[(lt-128)*2+1] = gU2[(lt-128)*2+1];
    }
    if (lt < 62) U1_s[lt] = gU1[lt];
    else if (lt >= 64 && lt < 69)  U3_s[lt-64] = gU3[lt-64];
    else if (lt >= 70 && lt < 79)  be_s[lt-70] = gbe[lt-70];
    else if (lt >= 80 && lt < 89)  Ve_s[lt-80] = gVe[lt-80];
    else if (lt >= 90 && lt < 93)  W1_s[lt-90] = gW1[lt-90];
    else if (lt >= 96 && lt < 111) W2_s[lt-96] = gW2[lt-96];
    else if (lt >= 112 && lt < 117) W3_s[lt-112] = gW3[lt-112];
    else if (lt >= 118 && lt < 123) a_s[lt-118] = ga[lt-118];
    __syncthreads();

    // P1: y + rhs
    if (lt < 15) {
        int t = lt/5, f = lt%5;
        float s = 0.f;
        for (int v = 0; v < 62; v++) s += sx[t*310+v*5+f]*U1_s[v];
        y_s[t*5+f] = s;
    }
    if (lt >= 32 && lt < 218) {
        int r = lt-32;
        int v = r/3, t = r%3;
        const float* xr = sx + t*310 + v*5;
        float s = 0.f;
        #pragma unroll
        for (int f=0; f<5; f++) s += U3_s[f]*xr[f];
        rhs_s[v*3+t] = s;
    }
    __syncthreads();
    // P2: lhs
    if (lt < 186) {
        int t = lt/62, u = lt%62;
        float s = 0.f;
        #pragma unroll
        for (int f=0; f<5; f++) s += y_s[t*5+f]*U2_s[f*62+u];
        lhs_s[t*62+u] = s;
    }
    __syncthreads();
    // P3: prod
    if (lt < 9) {
        int t = lt/3, u = lt%3;
        float s = 0.f;
        for (int v=0; v<62; v++) s += lhs_s[t*62+v]*rhs_s[v*3+u];
        prod_s[t*3+u] = s;
    }
    __syncthreads();
    // P4: E
    if (lt < 9) {
        int t = lt/3, u = lt%3;
        float s = 0.f;
        #pragma unroll
        for (int k=0; k<3; k++) s += Ve_s[t*3+k]*fsig(prod_s[k*3+u]+be_s[k*3+u]);
        E_s[t*3+u] = s;
    }
    __syncthreads();
    // P5: softmax over t
    if (lt < 3) {
        int u = lt;
        float m = fmaxf(E_s[u], fmaxf(E_s[3+u], E_s[6+u]));
        float e0=__expf(E_s[u]-m), e1=__expf(E_s[3+u]-m), e2=__expf(E_s[6+u]-m);
        float inv = __fdividef(1.0f, e0+e1+e2);
        At_s[u]=e0*inv; At_s[3+u]=e1*inv; At_s[6+u]=e2*inv;
    }
    __syncthreads();
    // P6: x_TAt
    for (int i = lt; i < 930; i += 256) {
        int u = i/310, r = i%310;
        sxT[i] = (sx[r]*At_s[u] + sx[310+r]*At_s[3+u] + sx[620+r]*At_s[6+u]) * 0.056796183f;
    }
    __syncthreads();
    // P7: slhs + srhs
    if (lt < 186) {
        int v = lt/3, s = lt%3;
        float acc = 0.f;
        #pragma unroll
        for (int f=0; f<5; f++) {
            float yv = sxT[v*5+f]*W1_s[0] + sxT[310+v*5+f]*W1_s[1] + sxT[620+v*5+f]*W1_s[2];
            acc += yv*W2_s[f*3+s];
        }
        slhs_s[v*3+s] = acc;
        int t = lt/62, vv = lt%62;
        const float* xr = sxT + t*310 + vv*5;
        float s2 = 0.f;
        #pragma unroll
        for (int f=0; f<5; f++) s2 += W3_s[f]*xr[f];
        srhs_s[t*62+vv] = s2;
    }
    __syncthreads();
    // P8: sigmoid map [w][v] stride 64
    for (int i = lt; i < 3844; i += 256) {
        int w = i/62, v = i%62;
        float p = slhs_s[w*3]*srhs_s[v] + slhs_s[w*3+1]*srhs_s[62+v]
                + slhs_s[w*3+2]*srhs_s[124+v] + gbs[i];
        bufA[w*64+v] = fsig(p);
    }
    if (lt < 62) { bufA[lt*64+62]=0.f; bufA[lt*64+63]=0.f; }
    __syncthreads();
    // P9: Sm matmul (2u x 8v tile), Vs via L1
    {
        int u2 = lt>>3;
        int vq = lt&7;
        int u0 = u2*2;
        if (u0 < 62) {
            float acc[16];
            #pragma unroll
            for (int k=0;k<16;k++) acc[k]=0.f;
            const float* va_p = gVs + u0*62;
            const float* vb_p = va_p + 62;
            for (int w=0; w<62; w++) {
                float va = __ldg(va_p + w);
                float vb = __ldg(vb_p + w);
                const float4* rowp = reinterpret_cast<const float4*>(bufA + w*64 + vq*8);
                float4 s0 = rowp[0], s1 = rowp[1];
                float sv[8] = {s0.x,s0.y,s0.z,s0.w,s1.x,s1.y,s1.z,s1.w};
                #pragma unroll
                for (int j=0;j<8;j++) { acc[j] += va*sv[j]; acc[8+j] += vb*sv[j]; }
            }
            #pragma unroll
            for (int j=0;j<8;j++) {
                int v = vq*8+j;
                if (v < 62) {
                    bufAt[u0*62+v]     = acc[j];
                    bufAt[(u0+1)*62+v] = acc[8+j];
                }
            }
        }
    }
    __syncthreads();
    // P10: softmax over u per column v (4 lanes/col)
    {
        int v = lt>>2, g = lt&3;
        bool act = (v < 62);
        float m = -1e30f;
        if (act) for (int u=g; u<62; u+=4) m = fmaxf(m, bufAt[u*62+v]);
        m = fmaxf(m, __shfl_xor_sync(0xffffffffu, m, 1));
        m = fmaxf(m, __shfl_xor_sync(0xffffffffu, m, 2));
        float ssum = 0.f;
        if (act) for (int u=g; u<62; u+=4) { float e = __expf(bufAt[u*62+v]-m); bufAt[u*62+v]=e; ssum+=e; }
        ssum += __shfl_xor_sync(0xffffffffu, ssum, 1);
        ssum += __shfl_xor_sync(0xffffffffu, ssum, 2);
        float inv = __fdividef(1.0f, ssum);
        if (act) for (int u=g; u<62; u+=4) bufAt[u*62+v] *= inv;
    }
    __syncthreads();
    // P11: tmpS (reuse bufA, stride 62)
    const float* xm = sx + 310;
    {
        float a0=a_s[0],a1=a_s[1],a2=a_s[2],a3=a_s[3],a4=a_s[4];
        for (int i = lt; i < 3844; i += 256) {
            int ii = i/62, jj = i%62;
            const float* xi = xm + ii*5; const float* xj = xm + jj*5;
            float e = fabsf(xi[0]-xj[0])*a0 + fabsf(xi[1]-xj[1])*a1 + fabsf(xi[2]-xj[2])*a2
                    + fabsf(xi[3]-xj[3])*a3 + fabsf(xi[4]-xj[4])*a4;
            bufA[i] = __expf(fmaxf(e, 0.0f));
        }
    }
    __syncthreads();
    // P12: column reciprocal
    {
        int j = lt>>2, g = lt&3;
        bool act = (j < 62);
        float cs = 0.f;
        if (act) for (int i=g; i<62; i+=4) cs += bufA[i*62+j];
        cs += __shfl_xor_sync(0xffffffffu, cs, 1);
        cs += __shfl_xor_sync(0xffffffffu, cs, 2);
        if (act && g==0) colsum[j] = __fdividef(1.0f, cs);
    }
    __syncthreads();
    // P13: normalize + store S
    for (int i = lt; i < 3844; i += 256) {
        float s = bufA[i] * colsum[i%62];
        bufA[i] = s;
        out[S_BASE + (size_t)b*3844 + i] = s;
    }
    __syncthreads();
    // P14: Dg + d2
    {
        int j = lt>>2, g = lt&3;
        bool act = (j < 62);
        float cs = 0.f, dd = 0.f;
        if (act) {
            const float* xj = xm + j*5;
            for (int i=g; i<62; i+=4) {
                cs += bufA[i*62+j];
                const float* xi = xm + i*5;
                #pragma unroll
                for (int f=0; f<5; f++) { float d = xj[f]-xi[f]; dd += d*d; }
            }
        }
        cs += __shfl_xor_sync(0xffffffffu, cs, 1);
        cs += __shfl_xor_sync(0xffffffffu, cs, 2);
        dd += __shfl_xor_sync(0xffffffffu, dd, 1);
        dd += __shfl_xor_sync(0xffffffffu, dd, 2);
        if (act && g==0) { DgS_s[j] = cs; d2s_s[j] = dd; }
    }
    __syncthreads();
    // P15: Sloss partials
    {
        float sl = 0.f;
        for (int i = lt; i < 3844; i += 256) sl += bufA[i]*bufA[i];
        #pragma unroll
        for (int o=16; o; o>>=1) sl += __shfl_xor_sync(0xffffffffu, sl, o);
        if ((lt&31)==0) red_s[lt>>5] = sl;
    }
    __syncthreads();
    // P16: cheb accumulators -> g_acc [b][tv][16] + loss finalize
    if (lt < 186) {
        int t = lt/62, v = lt%62;
        float acc[15];
        #pragma unroll
        for (int k=0;k<15;k++) acc[k]=0.f;
        float dgm1 = DgS_s[v] - 1.0f;
        for (int u=0; u<62; u++) {
            float s  = bufA[u*62+v];
            float at = bufAt[u*62+v];
            float delta = (u==v) ? 1.0f : 0.0f;
            float lt_ = dgm1*delta - s;
            float c2 = 2.0f*lt_*lt_ - delta;
            float t0 = delta*at, t1 = lt_*at, t2 = c2*at;
            const float* xr = sx + t*310 + u*5;
            #pragma unroll
            for (int f=0; f<5; f++) {
                float xv = xr[f];
                acc[f]    += t0*xv;
                acc[5+f]  += t1*xv;
                acc[10+f] += t2*xv;
            }
        }
        float4* gp = reinterpret_cast<float4*>(g_acc + (size_t)b*2976 + (size_t)(t*62+v)*16);
        gp[0] = make_float4(acc[0],acc[1],acc[2],acc[3]);
        gp[1] = make_float4(acc[4],acc[5],acc[6],acc[7]);
        gp[2] = make_float4(acc[8],acc[9],acc[10],acc[11]);
        gp[3] = make_float4(acc[12],acc[13],acc[14],0.0f);
    } else if (lt == 192) {
        float sl = 0.f;
        #pragma unroll
        for (int w=0; w<8; w++) sl += red_s[w];
        atomicAdd(out + XR_ELEMS, sl * (ALPHA/(float)NBATCH));
        float dp = 0.f;
        for (int j=0; j<62; j++) dp += DgS_s[j]*d2s_s[j];
        atomicAdd(out + XR_ELEMS + 1, dp * ALPHA);
    }
}

// ============ K3: phases 4b-6, 2 batches per block ============
__global__ void __launch_bounds__(512,3) stgcn_k3(
    const float* __restrict__ gx, const float* __restrict__ gTheta,
    const float* __restrict__ gtb, const float* __restrict__ grw,
    const float* __restrict__ grb, const float* __restrict__ ggamma,
    const float* __restrict__ gbeta, float* __restrict__ out)
{
    extern __shared__ float smarr[];
    const int tid = threadIdx.x;
    const int b0 = blockIdx.x*2;

    float* sg    = smarr;              // 12288 [t][c][v] rowstride 64
    float* zb    = sg   + 12288;       // 4032  z [v][o] rowstride 65
    float* Th_s  = zb   + 4032;        // 960   [kf][o]
    float* x0_s  = Th_s + 960;         // 320
    float* tb_s  = x0_s + 320;         // 64
    float* rb_s  = tb_s + 64;          // 64
    float* rw_s  = rb_s + 64;          // 320
    float* gam_s = rw_s + 320;         // 64
    float* bet_s = gam_s+ 64;          // 64
    float* mu_s  = bet_s+ 64;          // 64
    float* iv_s  = mu_s + 64;          // 64

    for (int i = tid; i < 960; i += 512) Th_s[i] = gTheta[i];
    for (int i = tid; i < 320; i += 512) rw_s[i] = grw[i];
    if (tid < 64) { tb_s[tid]=gtb[tid]; rb_s[tid]=grb[tid]; gam_s[tid]=ggamma[tid]; bet_s[tid]=gbeta[tid]; }

    for (int bi = 0; bi < 2; bi++) {
        const int b = b0 + bi;
        for (int i = tid; i < 310; i += 512) x0_s[i] = gx[(size_t)b*930 + i];
        // (sync below covers x0_s and, on bi=0, all staged weights)

        // Phase 4b: Theta contraction -> sg (float4 Th loads)
        // x0_s/Th_s must be visible and previous batch's phase-6 reads done:
        __syncthreads();
        if (tid < 372) {
            int oh = (tid >= 186);
            int r = tid - oh*186;
            int t = r/62, v = r%62;
            int tv = t*62+v;
            const float4* ap4 = reinterpret_cast<const float4*>(g_acc + (size_t)b*2976 + (size_t)tv*16);
            float4 A0=__ldg(ap4), A1=__ldg(ap4+1), A2=__ldg(ap4+2), A3=__ldg(ap4+3);
            float a0[15] = {A0.x,A0.y,A0.z,A0.w, A1.x,A1.y,A1.z,A1.w,
                            A2.x,A2.y,A2.z,A2.w, A3.x,A3.y,A3.z};
            const float4* Th4 = reinterpret_cast<const float4*>(Th_s);  // [kf][16]
            int qb = oh*8;
            float* sgr = sg + t*4096 + v;
            #pragma unroll 2
            for (int q=0; q<8; q++) {
                int oq = qb+q;
                float zx=0.f, zy=0.f, zz=0.f, zw=0.f;
                #pragma unroll
                for (int kf=0; kf<15; kf++) {
                    float4 th = Th4[kf*16+oq];
                    float av = a0[kf];
                    zx += av*th.x; zy += av*th.y; zz += av*th.z; zw += av*th.w;
                }
                int o0 = oq*4;
                sgr[(o0  )*64] = fmaxf(zx, 0.0f);
                sgr[(o0+1)*64] = fmaxf(zy, 0.0f);
                sgr[(o0+2)*64] = fmaxf(zz, 0.0f);
                sgr[(o0+3)*64] = fmaxf(zw, 0.0f);
            }
        }
        for (int i = tid; i < 192; i += 512) {
            int t = i/64, c = i%64;
            sg[t*4096 + c*64 + 62] = 0.f;
            sg[t*4096 + c*64 + 63] = 0.f;
        }
        __syncthreads();

        // Phase 5: temporal conv — 8o x 2v per thread, 2-way k-split, tw via L1
        {
            int og  = tid & 7;            // o-group: o = og*8..+8
            int kh  = (tid >> 3) & 1;     // k-half
            int vg  = tid >> 4;           // 0..31
            int o0  = og*8;
            int v0  = vg*2;
            float acc[16];                // [vj*8+oi]
            #pragma unroll
            for (int k=0;k<16;k++) acc[k]=0.f;
            int tc0 = kh*96;
            #pragma unroll 4
            for (int tc = tc0; tc < tc0+96; tc++) {
                int t = tc>>6, c = tc&63;
                float2 sv = *reinterpret_cast<const float2*>(sg + t*4096 + c*64 + v0);
                const float4* twp = reinterpret_cast<const float4*>(g_twt + (t<<12) + (c<<6) + o0);
                float4 w0 = __ldg(twp), w1 = __ldg(twp+1);
                acc[0]  += sv.x*w0.x; acc[1]  += sv.x*w0.y; acc[2]  += sv.x*w0.z; acc[3]  += sv.x*w0.w;
                acc[4]  += sv.x*w1.x; acc[5]  += sv.x*w1.y; acc[6]  += sv.x*w1.z; acc[7]  += sv.x*w1.w;
                acc[8]  += sv.y*w0.x; acc[9]  += sv.y*w0.y; acc[10] += sv.y*w0.z; acc[11] += sv.y*w0.w;
                acc[12] += sv.y*w1.x; acc[13] += sv.y*w1.y; acc[14] += sv.y*w1.z; acc[15] += sv.y*w1.w;
            }
            #pragma unroll
            for (int k=0;k<16;k++) acc[k] += __shfl_xor_sync(0xffffffffu, acc[k], 8);
            if (kh == 0 && v0 < 62) {
                #pragma unroll
                for (int vj=0; vj<2; vj++) {
                    int v = v0+vj;
                    if (v < 62) {
                        const float* x0 = x0_s + v*5;
                        float xa=x0[0], xb=x0[1], xc=x0[2], xd=x0[3], xe=x0[4];
                        #pragma unroll
                        for (int oi=0; oi<8; oi++) {
                            int o = o0+oi;
                            float tcv = (acc[vj*8+oi] + tb_s[o]) * 0.25819889f;
                            const float* rwp = rw_s + o*5;
                            float resv = rb_s[o] + xa*rwp[0]+xb*rwp[1]+xc*rwp[2]+xd*rwp[3]+xe*rwp[4];
                            zb[v*65+o] = fmaxf(resv + tcv, 0.0f);
                        }
                    }
                }
            }
        }
        __syncthreads();

        // Phase 6: LayerNorm + writeback
        {
            int v = tid>>3, g = tid&7;
            bool act = (v < 62);
            float s = 0.f;
            if (act) for (int o=g; o<64; o+=8) s += zb[v*65+o];
            #pragma unroll
            for (int o=4; o; o>>=1) s += __shfl_xor_sync(0xffffffffu, s, o);
            float mu = s * (1.0f/64.0f);
            float vv = 0.f;
            if (act) for (int o=g; o<64; o+=8) { float d = zb[v*65+o]-mu; vv += d*d; }
            #pragma unroll
            for (int o=4; o; o>>=1) vv += __shfl_xor_sync(0xffffffffu, vv, o);
            vv *= (1.0f/64.0f);
            if (act && g==0) { mu_s[v] = mu; iv_s[v] = rsqrtf(vv + LN_EPS); }
        }
        __syncthreads();
        for (int i = tid; i < 3968; i += 512) {
            int v = i>>6, o = i&63;
            float val = (zb[v*65+o]-mu_s[v])*iv_s[v]*gam_s[o] + bet_s[o];
            out[(size_t)b*3968 + i] = val;
        }
        // loop back: next batch's x0_s load happens before a fresh __syncthreads
    }
}

#define SMEM_A_BYTES (11124*4)
#define SMEM_K3_BYTES (18304*4)

extern "C" void kernel_launch(void* const* d_in, const int* in_sizes, int n_in,
                              void* d_out, int out_size) {
    const float* x     = (const float*)d_in[0];
    const float* U1    = (const float*)d_in[1];
    const float* U2    = (const float*)d_in[2];
    const float* U3    = (const float*)d_in[3];
    const float* be    = (const float*)d_in[4];
    const float* Ve    = (const float*)d_in[5];
    const float* W1    = (const float*)d_in[6];
    const float* W2    = (const float*)d_in[7];
    const float* W3    = (const float*)d_in[8];
    const float* bs    = (const float*)d_in[9];
    const float* Vs    = (const float*)d_in[10];
    const float* a     = (const float*)d_in[11];
    const float* Theta = (const float*)d_in[12];
    const float* tw    = (const float*)d_in[13];
    const float* tb    = (const float*)d_in[14];
    const float* rw    = (const float*)d_in[15];
    const float* rb    = (const float*)d_in[16];
    const float* gamma = (const float*)d_in[17];
    const float* beta  = (const float*)d_in[18];
    float* out = (float*)d_out;

    cudaFuncSetAttribute(stgcn_a,  cudaFuncAttributeMaxDynamicSharedMemorySize, SMEM_A_BYTES);
    cudaFuncSetAttribute(stgcn_k3, cudaFuncAttributeMaxDynamicSharedMemorySize, SMEM_K3_BYTES);

    prep_kernel<<<48, 256>>>(tw, out);
    stgcn_a<<<NBATCH, 256, SMEM_A_BYTES>>>(x, U1, U2, U3, be, Ve, W1, W2, W3,
                                           bs, Vs, a, out);
    stgcn_k3<<<NBATCH/2, 512, SMEM_K3_BYTES>>>(x, Theta, tb, rw, rb, gamma, beta, out);
}

// round 14
// speedup vs baseline: 1.7392x; 1.2645x over previous
#include <cuda_runtime.h>
#include <cuda_bf16.h>
#include <math.h>

#define NBATCH 2048
#define ALPHA 1e-4f
#define LN_EPS 1e-5f

#define XR_ELEMS (NBATCH*62*64)      /* 8126464 */
#define S_BASE   (XR_ELEMS + 2)

// Scratch: per-batch cheb accumulators [b][tv][16] (kf-contig, padded), transposed tw.
__device__ float g_acc[NBATCH*2976];
__device__ float g_twt[12288];           // [t*64+c][o]

__device__ __forceinline__ float fsig(float x){ return __fdividef(1.0f, 1.0f+__expf(-x)); }

__global__ void prep_kernel(const float* __restrict__ gtw, float* __restrict__ out) {
    int i = blockIdx.x*256 + threadIdx.x;
    if (i < 12288) {
        int o = i/192, c = (i%192)/3, t = i%3;
        g_twt[(t*64+c)*64+o] = gtw[i];
    }
    if (i < 2) out[XR_ELEMS + i] = 0.0f;
}

// ============ KERNEL A: phases 0-4a, 256 threads, 1 batch/block ============
__global__ void __launch_bounds__(256,5) stgcn_a(
    const float* __restrict__ gx, const float* __restrict__ gU1,
    const float* __restrict__ gU2, const float* __restrict__ gU3,
    const float* __restrict__ gbe, const float* __restrict__ gVe,
    const float* __restrict__ gW1, const float* __restrict__ gW2,
    const float* __restrict__ gW3, const float* __restrict__ gbs,
    const float* __restrict__ gVs, const float* __restrict__ ga,
    float* __restrict__ out)
{
    extern __shared__ float smarr[];
    const int lt = threadIdx.x;
    const int b  = blockIdx.x;

    float* sx    = smarr;            // 932
    float* sxT   = sx   + 932;       // 932
    float* bufA  = sxT  + 932;       // 3968
    float* bufAt = bufA + 3968;      // 3844
    float* y_s   = bufAt+ 3844;      // 16
    float* lhs_s = y_s  + 16;        // 188
    float* rhs_s = lhs_s+ 188;       // 188
    float* prod_s= rhs_s+ 188;       // 12
    float* E_s   = prod_s+12;        // 12
    float* At_s  = E_s  + 12;        // 12
    float* slhs_s= At_s + 12;        // 188
    float* srhs_s= slhs_s+188;       // 188
    float* colsum= srhs_s+188;       // 64
    float* DgS_s = colsum+ 64;       // 64
    float* d2s_s = DgS_s + 64;       // 64
    float* red_s = d2s_s + 64;       // 8
    float* U2_s  = red_s + 8;        // 312
    float* U1_s  = U2_s + 312;       // 64
    float* U3_s  = U1_s + 64;        // 8
    float* be_s  = U3_s + 8;         // 12
    float* Ve_s  = be_s + 12;        // 12
    float* W1_s  = Ve_s + 12;        // 4
    float* W2_s  = W1_s + 4;         // 16
    float* W3_s  = W2_s + 16;        // 8
    float* a_s   = W3_s + 8;         // 8

    for (int i = lt; i < 930; i += 256) sx[i] = gx[(size_t)b*930 + i];
    if (lt >= 128 && lt < 128+155) {
        U2_s[(lt-128)*2]   = gU2[(lt-128)*2];
        U2_s[(lt-128)*2+1] = gU2[(lt-128)*2+1];
    }
    if (lt < 62) U1_s[lt] = gU1[lt];
    else if (lt >= 64 && lt < 69)  U3_s[lt-64] = gU3[lt-64];
    else if (lt >= 70 && lt < 79)  be_s[lt-70] = gbe[lt-70];
    else if (lt >= 80 && lt < 89)  Ve_s[lt-80] = gVe[lt-80];
    else if (lt >= 90 && lt < 93)  W1_s[lt-90] = gW1[lt-90];
    else if (lt >= 96 && lt < 111) W2_s[lt-96] = gW2[lt-96];
    else if (lt >= 112 && lt < 117) W3_s[lt-112] = gW3[lt-112];
    else if (lt >= 118 && lt < 123) a_s[lt-118] = ga[lt-118];
    __syncthreads();

    // P1: y + rhs
    if (lt < 15) {
        int t = lt/5, f = lt%5;
        float s = 0.f;
        for (int v = 0; v < 62; v++) s += sx[t*310+v*5+f]*U1_s[v];
        y_s[t*5+f] = s;
    }
    if (lt >= 32 && lt < 218) {
        int r = lt-32;
        int v = r/3, t = r%3;
        const float* xr = sx + t*310 + v*5;
        float s = 0.f;
        #pragma unroll
        for (int f=0; f<5; f++) s += U3_s[f]*xr[f];
        rhs_s[v*3+t] = s;
    }
    __syncthreads();
    // P2: lhs
    if (lt < 186) {
        int t = lt/62, u = lt%62;
        float s = 0.f;
        #pragma unroll
        for (int f=0; f<5; f++) s += y_s[t*5+f]*U2_s[f*62+u];
        lhs_s[t*62+u] = s;
    }
    __syncthreads();
    // P3: prod
    if (lt < 9) {
        int t = lt/3, u = lt%3;
        float s = 0.f;
        for (int v=0; v<62; v++) s += lhs_s[t*62+v]*rhs_s[v*3+u];
        prod_s[t*3+u] = s;
    }
    __syncthreads();
    // P4: E
    if (lt < 9) {
        int t = lt/3, u = lt%3;
        float s = 0.f;
        #pragma unroll
        for (int k=0; k<3; k++) s += Ve_s[t*3+k]*fsig(prod_s[k*3+u]+be_s[k*3+u]);
        E_s[t*3+u] = s;
    }
    __syncthreads();
    // P5: softmax over t
    if (lt < 3) {
        int u = lt;
        float m = fmaxf(E_s[u], fmaxf(E_s[3+u], E_s[6+u]));
        float e0=__expf(E_s[u]-m), e1=__expf(E_s[3+u]-m), e2=__expf(E_s[6+u]-m);
        float inv = __fdividef(1.0f, e0+e1+e2);
        At_s[u]=e0*inv; At_s[3+u]=e1*inv; At_s[6+u]=e2*inv;
    }
    __syncthreads();
    // P6: x_TAt
    for (int i = lt; i < 930; i += 256) {
        int u = i/310, r = i%310;
        sxT[i] = (sx[r]*At_s[u] + sx[310+r]*At_s[3+u] + sx[620+r]*At_s[6+u]) * 0.056796183f;
    }
    __syncthreads();
    // P7: slhs + srhs
    if (lt < 186) {
        int v = lt/3, s = lt%3;
        float acc = 0.f;
        #pragma unroll
        for (int f=0; f<5; f++) {
            float yv = sxT[v*5+f]*W1_s[0] + sxT[310+v*5+f]*W1_s[1] + sxT[620+v*5+f]*W1_s[2];
            acc += yv*W2_s[f*3+s];
        }
        slhs_s[v*3+s] = acc;
        int t = lt/62, vv = lt%62;
        const float* xr = sxT + t*310 + vv*5;
        float s2 = 0.f;
        #pragma unroll
        for (int f=0; f<5; f++) s2 += W3_s[f]*xr[f];
        srhs_s[t*62+vv] = s2;
    }
    __syncthreads();
    // P8: sigmoid map [w][v] stride 64
    for (int i = lt; i < 3844; i += 256) {
        int w = i/62, v = i%62;
        float p = slhs_s[w*3]*srhs_s[v] + slhs_s[w*3+1]*srhs_s[62+v]
                + slhs_s[w*3+2]*srhs_s[124+v] + gbs[i];
        bufA[w*64+v] = fsig(p);
    }
    if (lt < 62) { bufA[lt*64+62]=0.f; bufA[lt*64+63]=0.f; }
    __syncthreads();
    // P9: Sm matmul (2u x 8v tile), Vs via L1
    {
        int u2 = lt>>3;
        int vq = lt&7;
        int u0 = u2*2;
        if (u0 < 62) {
            float acc[16];
            #pragma unroll
            for (int k=0;k<16;k++) acc[k]=0.f;
            const float* va_p = gVs + u0*62;
            const float* vb_p = va_p + 62;
            for (int w=0; w<62; w++) {
                float va = __ldg(va_p + w);
                float vb = __ldg(vb_p + w);
                const float4* rowp = reinterpret_cast<const float4*>(bufA + w*64 + vq*8);
                float4 s0 = rowp[0], s1 = rowp[1];
                float sv[8] = {s0.x,s0.y,s0.z,s0.w,s1.x,s1.y,s1.z,s1.w};
                #pragma unroll
                for (int j=0;j<8;j++) { acc[j] += va*sv[j]; acc[8+j] += vb*sv[j]; }
            }
            #pragma unroll
            for (int j=0;j<8;j++) {
                int v = vq*8+j;
                if (v < 62) {
                    bufAt[u0*62+v]     = acc[j];
                    bufAt[(u0+1)*62+v] = acc[8+j];
                }
            }
        }
    }
    __syncthreads();
    // P10: softmax over u per column v (4 lanes/col)
    {
        int v = lt>>2, g = lt&3;
        bool act = (v < 62);
        float m = -1e30f;
        if (act) for (int u=g; u<62; u+=4) m = fmaxf(m, bufAt[u*62+v]);
        m = fmaxf(m, __shfl_xor_sync(0xffffffffu, m, 1));
        m = fmaxf(m, __shfl_xor_sync(0xffffffffu, m, 2));
        float ssum = 0.f;
        if (act) for (int u=g; u<62; u+=4) { float e = __expf(bufAt[u*62+v]-m); bufAt[u*62+v]=e; ssum+=e; }
        ssum += __shfl_xor_sync(0xffffffffu, ssum, 1);
        ssum += __shfl_xor_sync(0xffffffffu, ssum, 2);
        float inv = __fdividef(1.0f, ssum);
        if (act) for (int u=g; u<62; u+=4) bufAt[u*62+v] *= inv;
    }
    __syncthreads();
    // P11: tmpS (reuse bufA, stride 62)
    const float* xm = sx + 310;
    {
        float a0=a_s[0],a1=a_s[1],a2=a_s[2],a3=a_s[3],a4=a_s[4];
        for (int i = lt; i < 3844; i += 256) {
            int ii = i/62, jj = i%62;
            const float* xi = xm + ii*5; const float* xj = xm + jj*5;
            float e = fabsf(xi[0]-xj[0])*a0 + fabsf(xi[1]-xj[1])*a1 + fabsf(xi[2]-xj[2])*a2
                    + fabsf(xi[3]-xj[3])*a3 + fabsf(xi[4]-xj[4])*a4;
            bufA[i] = __expf(fmaxf(e, 0.0f));
        }
    }
    __syncthreads();
    // P12: column reciprocal
    {
        int j = lt>>2, g = lt&3;
        bool act = (j < 62);
        float cs = 0.f;
        if (act) for (int i=g; i<62; i+=4) cs += bufA[i*62+j];
        cs += __shfl_xor_sync(0xffffffffu, cs, 1);
        cs += __shfl_xor_sync(0xffffffffu, cs, 2);
        if (act && g==0) colsum[j] = __fdividef(1.0f, cs);
    }
    __syncthreads();
    // P13: normalize + store S
    for (int i = lt; i < 3844; i += 256) {
        float s = bufA[i] * colsum[i%62];
        bufA[i] = s;
        out[S_BASE + (size_t)b*3844 + i] = s;
    }
    __syncthreads();
    // P14: Dg + d2
    {
        int j = lt>>2, g = lt&3;
        bool act = (j < 62);
        float cs = 0.f, dd = 0.f;
        if (act) {
            const float* xj = xm + j*5;
            for (int i=g; i<62; i+=4) {
                cs += bufA[i*62+j];
                const float* xi = xm + i*5;
                #pragma unroll
                for (int f=0; f<5; f++) { float d = xj[f]-xi[f]; dd += d*d; }
            }
        }
        cs += __shfl_xor_sync(0xffffffffu, cs, 1);
        cs += __shfl_xor_sync(0xffffffffu, cs, 2);
        dd += __shfl_xor_sync(0xffffffffu, dd, 1);
        dd += __shfl_xor_sync(0xffffffffu, dd, 2);
        if (act && g==0) { DgS_s[j] = cs; d2s_s[j] = dd; }
    }
    __syncthreads();
    // P15: Sloss partials
    {
        float sl = 0.f;
        for (int i = lt; i < 3844; i += 256) sl += bufA[i]*bufA[i];
        #pragma unroll
        for (int o=16; o; o>>=1) sl += __shfl_xor_sync(0xffffffffu, sl, o);
        if ((lt&31)==0) red_s[lt>>5] = sl;
    }
    __syncthreads();
    // P16: cheb accumulators -> g_acc [b][tv][16] + loss finalize
    if (lt < 186) {
        int t = lt/62, v = lt%62;
        float acc[15];
        #pragma unroll
        for (int k=0;k<15;k++) acc[k]=0.f;
        float dgm1 = DgS_s[v] - 1.0f;
        for (int u=0; u<62; u++) {
            float s  = bufA[u*62+v];
            float at = bufAt[u*62+v];
            float delta = (u==v) ? 1.0f : 0.0f;
            float lt_ = dgm1*delta - s;
            float c2 = 2.0f*lt_*lt_ - delta;
            float t0 = delta*at, t1 = lt_*at, t2 = c2*at;
            const float* xr = sx + t*310 + u*5;
            #pragma unroll
            for (int f=0; f<5; f++) {
                float xv = xr[f];
                acc[f]    += t0*xv;
                acc[5+f]  += t1*xv;
                acc[10+f] += t2*xv;
            }
        }
        float4* gp = reinterpret_cast<float4*>(g_acc + (size_t)b*2976 + (size_t)(t*62+v)*16);
        gp[0] = make_float4(acc[0],acc[1],acc[2],acc[3]);
        gp[1] = make_float4(acc[4],acc[5],acc[6],acc[7]);
        gp[2] = make_float4(acc[8],acc[9],acc[10],acc[11]);
        gp[3] = make_float4(acc[12],acc[13],acc[14],0.0f);
    } else if (lt == 192) {
        float sl = 0.f;
        #pragma unroll
        for (int w=0; w<8; w++) sl += red_s[w];
        atomicAdd(out + XR_ELEMS, sl * (ALPHA/(float)NBATCH));
        float dp = 0.f;
        for (int j=0; j<62; j++) dp += DgS_s[j]*d2s_s[j];
        atomicAdd(out + XR_ELEMS + 1, dp * ALPHA);
    }
}

// ============ K3: phases 4b-6, bf16 sg, 4 blocks/SM ============
__global__ void __launch_bounds__(512,4) stgcn_k3(
    const float* __restrict__ gx, const float* __restrict__ gTheta,
    const float* __restrict__ gtb, const float* __restrict__ grw,
    const float* __restrict__ grb, const float* __restrict__ ggamma,
    const float* __restrict__ gbeta, float* __restrict__ out)
{
    extern __shared__ float smarr[];
    const int tid = threadIdx.x;
    const int b = blockIdx.x;

    __nv_bfloat16* sgb = reinterpret_cast<__nv_bfloat16*>(smarr);  // 12288 bf16 = 6144 floats
    float* zb    = smarr + 6144;       // 4032  z [v][o] rowstride 65
    float* Th_s  = zb   + 4032;        // 960   [kf][o]
    float* x0_s  = Th_s + 960;         // 320
    float* tb_s  = x0_s + 320;         // 64
    float* rb_s  = tb_s + 64;          // 64
    float* rw_s  = rb_s + 64;          // 320
    float* gam_s = rw_s + 320;         // 64
    float* bet_s = gam_s+ 64;          // 64
    float* mu_s  = bet_s+ 64;          // 64
    float* iv_s  = mu_s + 64;          // 64

    for (int i = tid; i < 960; i += 512) Th_s[i] = gTheta[i];
    for (int i = tid; i < 310; i += 512) x0_s[i] = gx[(size_t)b*930 + i];
    for (int i = tid; i < 320; i += 512) rw_s[i] = grw[i];
    if (tid < 64) { tb_s[tid]=gtb[tid]; rb_s[tid]=grb[tid]; gam_s[tid]=ggamma[tid]; bet_s[tid]=gbeta[tid]; }
    __syncthreads();

    // Phase 4b: Theta contraction -> sg (bf16 stores)
    if (tid < 372) {
        int oh = (tid >= 186);
        int r = tid - oh*186;
        int t = r/62, v = r%62;
        int tv = t*62+v;
        const float4* ap4 = reinterpret_cast<const float4*>(g_acc + (size_t)b*2976 + (size_t)tv*16);
        float4 A0=__ldg(ap4), A1=__ldg(ap4+1), A2=__ldg(ap4+2), A3=__ldg(ap4+3);
        float a0[15] = {A0.x,A0.y,A0.z,A0.w, A1.x,A1.y,A1.z,A1.w,
                        A2.x,A2.y,A2.z,A2.w, A3.x,A3.y,A3.z};
        const float4* Th4 = reinterpret_cast<const float4*>(Th_s);  // [kf][16]
        int qb = oh*8;
        __nv_bfloat16* sgr = sgb + t*4096 + v;
        #pragma unroll 2
        for (int q=0; q<8; q++) {
            int oq = qb+q;
            float zx=0.f, zy=0.f, zz=0.f, zw=0.f;
            #pragma unroll
            for (int kf=0; kf<15; kf++) {
                float4 th = Th4[kf*16+oq];
                float av = a0[kf];
                zx += av*th.x; zy += av*th.y; zz += av*th.z; zw += av*th.w;
            }
            int o0 = oq*4;
            sgr[(o0  )*64] = __float2bfloat16(fmaxf(zx, 0.0f));
            sgr[(o0+1)*64] = __float2bfloat16(fmaxf(zy, 0.0f));
            sgr[(o0+2)*64] = __float2bfloat16(fmaxf(zz, 0.0f));
            sgr[(o0+3)*64] = __float2bfloat16(fmaxf(zw, 0.0f));
        }
    }
    for (int i = tid; i < 192; i += 512) {
        int t = i/64, c = i%64;
        sgb[t*4096 + c*64 + 62] = __float2bfloat16(0.0f);
        sgb[t*4096 + c*64 + 63] = __float2bfloat16(0.0f);
    }
    __syncthreads();

    // Phase 5: temporal conv — 4o x 2v per thread, no k-split, tw via L1
    {
        int og  = tid & 15;           // o0 = og*4
        int vg  = tid >> 4;           // 0..31, v0 = vg*2
        int o0  = og*4;
        int v0  = vg*2;
        float acc[8];                 // [vj*4+oi]
        #pragma unroll
        for (int k=0;k<8;k++) acc[k]=0.f;
        #pragma unroll 2
        for (int tc = 0; tc < 192; tc++) {
            int t = tc>>6, c = tc&63;
            __nv_bfloat162 sv2 = *reinterpret_cast<const __nv_bfloat162*>(sgb + t*4096 + c*64 + v0);
            float2 sv = __bfloat1622float2(sv2);
            float4 w0 = __ldg(reinterpret_cast<const float4*>(g_twt + (t<<12) + (c<<6) + o0));
            acc[0] += sv.x*w0.x; acc[1] += sv.x*w0.y; acc[2] += sv.x*w0.z; acc[3] += sv.x*w0.w;
            acc[4] += sv.y*w0.x; acc[5] += sv.y*w0.y; acc[6] += sv.y*w0.z; acc[7] += sv.y*w0.w;
        }
        #pragma unroll
        for (int vj=0; vj<2; vj++) {
            int v = v0+vj;
            if (v < 62) {
                const float* x0 = x0_s + v*5;
                float xa=x0[0], xb=x0[1], xc=x0[2], xd=x0[3], xe=x0[4];
                #pragma unroll
                for (int oi=0; oi<4; oi++) {
                    int o = o0+oi;
                    float tcv = (acc[vj*4+oi] + tb_s[o]) * 0.25819889f;
                    const float* rwp = rw_s + o*5;
                    float resv = rb_s[o] + xa*rwp[0]+xb*rwp[1]+xc*rwp[2]+xd*rwp[3]+xe*rwp[4];
                    zb[v*65+o] = fmaxf(resv + tcv, 0.0f);
                }
            }
        }
    }
    __syncthreads();

    // Phase 6: LayerNorm + writeback
    {
        int v = tid>>3, g = tid&7;
        bool act = (v < 62);
        float s = 0.f;
        if (act) for (int o=g; o<64; o+=8) s += zb[v*65+o];
        #pragma unroll
        for (int o=4; o; o>>=1) s += __shfl_xor_sync(0xffffffffu, s, o);
        float mu = s * (1.0f/64.0f);
        float vv = 0.f;
        if (act) for (int o=g; o<64; o+=8) { float d = zb[v*65+o]-mu; vv += d*d; }
        #pragma unroll
        for (int o=4; o; o>>=1) vv += __shfl_xor_sync(0xffffffffu, vv, o);
        vv *= (1.0f/64.0f);
        if (act && g==0) { mu_s[v] = mu; iv_s[v] = rsqrtf(vv + LN_EPS); }
    }
    __syncthreads();
    for (int i = tid; i < 3968; i += 512) {
        int v = i>>6, o = i&63;
        float val = (zb[v*65+o]-mu_s[v])*iv_s[v]*gam_s[o] + bet_s[o];
        out[(size_t)b*3968 + i] = val;
    }
}

#define SMEM_A_BYTES (11124*4)
#define SMEM_K3_BYTES (12160*4)

extern "C" void kernel_launch(void* const* d_in, const int* in_sizes, int n_in,
                              void* d_out, int out_size) {
    const float* x     = (const float*)d_in[0];
    const float* U1    = (const float*)d_in[1];
    const float* U2    = (const float*)d_in[2];
    const float* U3    = (const float*)d_in[3];
    const float* be    = (const float*)d_in[4];
    const float* Ve    = (const float*)d_in[5];
    const float* W1    = (const float*)d_in[6];
    const float* W2    = (const float*)d_in[7];
    const float* W3    = (const float*)d_in[8];
    const float* bs    = (const float*)d_in[9];
    const float* Vs    = (const float*)d_in[10];
    const float* a     = (const float*)d_in[11];
    const float* Theta = (const float*)d_in[12];
    const float* tw    = (const float*)d_in[13];
    const float* tb    = (const float*)d_in[14];
    const float* rw    = (const float*)d_in[15];
    const float* rb    = (const float*)d_in[16];
    const float* gamma = (const float*)d_in[17];
    const float* beta  = (const float*)d_in[18];
    float* out = (float*)d_out;

    cudaFuncSetAttribute(stgcn_a,  cudaFuncAttributeMaxDynamicSharedMemorySize, SMEM_A_BYTES);
    cudaFuncSetAttribute(stgcn_k3, cudaFuncAttributeMaxDynamicSharedMemorySize, SMEM_K3_BYTES);

    prep_kernel<<<48, 256>>>(tw, out);
    stgcn_a<<<NBATCH, 256, SMEM_A_BYTES>>>(x, U1, U2, U3, be, Ve, W1, W2, W3,
                                           bs, Vs, a, out);
    stgcn_k3<<<NBATCH, 512, SMEM_K3_BYTES>>>(x, Theta, tb, rw, rb, gamma, beta, out);
}

// round 15
// speedup vs baseline: 1.7582x; 1.0109x over previous
#include <cuda_runtime.h>
#include <cuda_bf16.h>
#include <math.h>

#define NBATCH 2048
#define ALPHA 1e-4f
#define LN_EPS 1e-5f

#define XR_ELEMS (NBATCH*62*64)      /* 8126464 */
#define S_BASE   (XR_ELEMS + 2)

// Scratch: per-batch cheb accumulators [b][tv][16] (kf-contig, padded), transposed tw.
__device__ float g_acc[NBATCH*2976];
__device__ float g_twt[12288];           // [t*64+c][o]

__device__ __forceinline__ float fsig(float x){ return __fdividef(1.0f, 1.0f+__expf(-x)); }

__global__ void prep_kernel(const float* __restrict__ gtw, float* __restrict__ out) {
    int i = blockIdx.x*256 + threadIdx.x;
    if (i < 12288) {
        int o = i/192, c = (i%192)/3, t = i%3;
        g_twt[(t*64+c)*64+o] = gtw[i];
    }
    if (i < 2) out[XR_ELEMS + i] = 0.0f;
}

// ============ KERNEL A: phases 0-4a, 256 threads, 6 blocks/SM (aliased smem) ============
__global__ void __launch_bounds__(256,6) stgcn_a(
    const float* __restrict__ gx, const float* __restrict__ gU1,
    const float* __restrict__ gU2, const float* __restrict__ gU3,
    const float* __restrict__ gbe, const float* __restrict__ gVe,
    const float* __restrict__ gW1, const float* __restrict__ gW2,
    const float* __restrict__ gW3, const float* __restrict__ gbs,
    const float* __restrict__ gVs, const float* __restrict__ ga,
    float* __restrict__ out)
{
    extern __shared__ float smarr[];
    const int lt = threadIdx.x;
    const int b  = blockIdx.x;

    // Persistent regions
    float* sx    = smarr;            // 936 (930 used, padded for 16B alignment of bufA)
    float* bufA  = sx   + 936;       // 3968 : sxT (P6-P7) -> sigmoid map (P8-P9) -> tmpS/S (P11+)
    float* bufAt = bufA + 3968;      // 3844 : early temporaries (P1-P7) -> Sm/spatial_At (P9+)
    float* slhs_s= bufAt+ 3844;      // 188
    float* srhs_s= slhs_s+188;       // 188
    float* colsum= srhs_s+188;       // 64
    float* DgS_s = colsum+ 64;       // 64
    float* d2s_s = DgS_s + 64;       // 64
    float* red_s = d2s_s + 64;       // 8
    float* a_s   = red_s + 8;        // 8
    // Aliased early temporaries (dead before P9) inside bufAt:
    float* sxT   = bufA;             // alias: x_TAt lives in bufA region until P7
    float* y_s   = bufAt + 0;        // 16
    float* lhs_s = bufAt + 16;       // 188
    float* rhs_s = bufAt + 204;      // 188
    float* prod_s= bufAt + 392;      // 12
    float* E_s   = bufAt + 404;      // 12
    float* At_s  = bufAt + 416;      // 12
    float* U2_s  = bufAt + 428;      // 312
    float* U1_s  = bufAt + 740;      // 64
    float* U3_s  = bufAt + 804;      // 8
    float* be_s  = bufAt + 812;      // 12
    float* Ve_s  = bufAt + 824;      // 12
    float* W1_s  = bufAt + 836;      // 4
    float* W2_s  = bufAt + 840;      // 16
    float* W3_s  = bufAt + 856;      // 8

    // ---------------- stage ----------------
    for (int i = lt; i < 930; i += 256) sx[i] = gx[(size_t)b*930 + i];
    if (lt >= 128 && lt < 128+155) {
        U2_s[(lt-128)*2]   = gU2[(lt-128)*2];
        U2_s[(lt-128)*2+1] = gU2[(lt-128)*2+1];
    }
    if (lt < 62) U1_s[lt] = gU1[lt];
    else if (lt >= 64 && lt < 69)  U3_s[lt-64] = gU3[lt-64];
    else if (lt >= 70 && lt < 79)  be_s[lt-70] = gbe[lt-70];
    else if (lt >= 80 && lt < 89)  Ve_s[lt-80] = gVe[lt-80];
    else if (lt >= 90 && lt < 93)  W1_s[lt-90] = gW1[lt-90];
    else if (lt >= 96 && lt < 111) W2_s[lt-96] = gW2[lt-96];
    else if (lt >= 112 && lt < 117) W3_s[lt-112] = gW3[lt-112];
    else if (lt >= 118 && lt < 123) a_s[lt-118] = ga[lt-118];
    __syncthreads();

    // P1: y + rhs
    if (lt < 15) {
        int t = lt/5, f = lt%5;
        float s = 0.f;
        for (int v = 0; v < 62; v++) s += sx[t*310+v*5+f]*U1_s[v];
        y_s[t*5+f] = s;
    }
    if (lt >= 32 && lt < 218) {
        int r = lt-32;
        int v = r/3, t = r%3;
        const float* xr = sx + t*310 + v*5;
        float s = 0.f;
        #pragma unroll
        for (int f=0; f<5; f++) s += U3_s[f]*xr[f];
        rhs_s[v*3+t] = s;
    }
    __syncthreads();
    // P2: lhs
    if (lt < 186) {
        int t = lt/62, u = lt%62;
        float s = 0.f;
        #pragma unroll
        for (int f=0; f<5; f++) s += y_s[t*5+f]*U2_s[f*62+u];
        lhs_s[t*62+u] = s;
    }
    __syncthreads();
    // P3: prod
    if (lt < 9) {
        int t = lt/3, u = lt%3;
        float s = 0.f;
        for (int v=0; v<62; v++) s += lhs_s[t*62+v]*rhs_s[v*3+u];
        prod_s[t*3+u] = s;
    }
    __syncthreads();
    // P4: E
    if (lt < 9) {
        int t = lt/3, u = lt%3;
        float s = 0.f;
        #pragma unroll
        for (int k=0; k<3; k++) s += Ve_s[t*3+k]*fsig(prod_s[k*3+u]+be_s[k*3+u]);
        E_s[t*3+u] = s;
    }
    __syncthreads();
    // P5: softmax over t
    if (lt < 3) {
        int u = lt;
        float m = fmaxf(E_s[u], fmaxf(E_s[3+u], E_s[6+u]));
        float e0=__expf(E_s[u]-m), e1=__expf(E_s[3+u]-m), e2=__expf(E_s[6+u]-m);
        float inv = __fdividef(1.0f, e0+e1+e2);
        At_s[u]=e0*inv; At_s[3+u]=e1*inv; At_s[6+u]=e2*inv;
    }
    __syncthreads();
    // P6: x_TAt -> sxT (bufA region)
    for (int i = lt; i < 930; i += 256) {
        int u = i/310, r = i%310;
        sxT[i] = (sx[r]*At_s[u] + sx[310+r]*At_s[3+u] + sx[620+r]*At_s[6+u]) * 0.056796183f;
    }
    __syncthreads();
    // P7: slhs + srhs (reads sxT + W's; writes persistent slhs/srhs)
    if (lt < 186) {
        int v = lt/3, s = lt%3;
        float acc = 0.f;
        #pragma unroll
        for (int f=0; f<5; f++) {
            float yv = sxT[v*5+f]*W1_s[0] + sxT[310+v*5+f]*W1_s[1] + sxT[620+v*5+f]*W1_s[2];
            acc += yv*W2_s[f*3+s];
        }
        slhs_s[v*3+s] = acc;
        int t = lt/62, vv = lt%62;
        const float* xr = sxT + t*310 + vv*5;
        float s2 = 0.f;
        #pragma unroll
        for (int f=0; f<5; f++) s2 += W3_s[f]*xr[f];
        srhs_s[t*62+vv] = s2;
    }
    __syncthreads();
    // P8: sigmoid map [w][v] stride 64 (overwrites sxT region)
    for (int i = lt; i < 3844; i += 256) {
        int w = i/62, v = i%62;
        float p = slhs_s[w*3]*srhs_s[v] + slhs_s[w*3+1]*srhs_s[62+v]
                + slhs_s[w*3+2]*srhs_s[124+v] + gbs[i];
        bufA[w*64+v] = fsig(p);
    }
    if (lt < 62) { bufA[lt*64+62]=0.f; bufA[lt*64+63]=0.f; }
    __syncthreads();
    // P9: Sm matmul (2u x 8v tile), Vs via L1 (overwrites early temps in bufAt)
    {
        int u2 = lt>>3;
        int vq = lt&7;
        int u0 = u2*2;
        if (u0 < 62) {
            float acc[16];
            #pragma unroll
            for (int k=0;k<16;k++) acc[k]=0.f;
            const float* va_p = gVs + u0*62;
            const float* vb_p = va_p + 62;
            for (int w=0; w<62; w++) {
                float va = __ldg(va_p + w);
                float vb = __ldg(vb_p + w);
                const float4* rowp = reinterpret_cast<const float4*>(bufA + w*64 + vq*8);
                float4 s0 = rowp[0], s1 = rowp[1];
                float sv[8] = {s0.x,s0.y,s0.z,s0.w,s1.x,s1.y,s1.z,s1.w};
                #pragma unroll
                for (int j=0;j<8;j++) { acc[j] += va*sv[j]; acc[8+j] += vb*sv[j]; }
            }
            #pragma unroll
            for (int j=0;j<8;j++) {
                int v = vq*8+j;
                if (v < 62) {
                    bufAt[u0*62+v]     = acc[j];
                    bufAt[(u0+1)*62+v] = acc[8+j];
                }
            }
        }
    }
    __syncthreads();
    // P10: softmax over u per column v (4 lanes/col)
    {
        int v = lt>>2, g = lt&3;
        bool act = (v < 62);
        float m = -1e30f;
        if (act) for (int u=g; u<62; u+=4) m = fmaxf(m, bufAt[u*62+v]);
        m = fmaxf(m, __shfl_xor_sync(0xffffffffu, m, 1));
        m = fmaxf(m, __shfl_xor_sync(0xffffffffu, m, 2));
        float ssum = 0.f;
        if (act) for (int u=g; u<62; u+=4) { float e = __expf(bufAt[u*62+v]-m); bufAt[u*62+v]=e; ssum+=e; }
        ssum += __shfl_xor_sync(0xffffffffu, ssum, 1);
        ssum += __shfl_xor_sync(0xffffffffu, ssum, 2);
        float inv = __fdividef(1.0f, ssum);
        if (act) for (int u=g; u<62; u+=4) bufAt[u*62+v] *= inv;
    }
    __syncthreads();
    // P11: tmpS (reuse bufA, stride 62)
    const float* xm = sx + 310;
    {
        float a0=a_s[0],a1=a_s[1],a2=a_s[2],a3=a_s[3],a4=a_s[4];
        for (int i = lt; i < 3844; i += 256) {
            int ii = i/62, jj = i%62;
            const float* xi = xm + ii*5; const float* xj = xm + jj*5;
            float e = fabsf(xi[0]-xj[0])*a0 + fabsf(xi[1]-xj[1])*a1 + fabsf(xi[2]-xj[2])*a2
                    + fabsf(xi[3]-xj[3])*a3 + fabsf(xi[4]-xj[4])*a4;
            bufA[i] = __expf(fmaxf(e, 0.0f));
        }
    }
    __syncthreads();
    // P12: column reciprocal
    {
        int j = lt>>2, g = lt&3;
        bool act = (j < 62);
        float cs = 0.f;
        if (act) for (int i=g; i<62; i+=4) cs += bufA[i*62+j];
        cs += __shfl_xor_sync(0xffffffffu, cs, 1);
        cs += __shfl_xor_sync(0xffffffffu, cs, 2);
        if (act && g==0) colsum[j] = __fdividef(1.0f, cs);
    }
    __syncthreads();
    // P13: normalize + store S
    for (int i = lt; i < 3844; i += 256) {
        float s = bufA[i] * colsum[i%62];
        bufA[i] = s;
        out[S_BASE + (size_t)b*3844 + i] = s;
    }
    __syncthreads();
    // P14: Dg + d2
    {
        int j = lt>>2, g = lt&3;
        bool act = (j < 62);
        float cs = 0.f, dd = 0.f;
        if (act) {
            const float* xj = xm + j*5;
            for (int i=g; i<62; i+=4) {
                cs += bufA[i*62+j];
                const float* xi = xm + i*5;
                #pragma unroll
                for (int f=0; f<5; f++) { float d = xj[f]-xi[f]; dd += d*d; }
            }
        }
        cs += __shfl_xor_sync(0xffffffffu, cs, 1);
        cs += __shfl_xor_sync(0xffffffffu, cs, 2);
        dd += __shfl_xor_sync(0xffffffffu, dd, 1);
        dd += __shfl_xor_sync(0xffffffffu, dd, 2);
        if (act && g==0) { DgS_s[j] = cs; d2s_s[j] = dd; }
    }
    __syncthreads();
    // P15: Sloss partials
    {
        float sl = 0.f;
        for (int i = lt; i < 3844; i += 256) sl += bufA[i]*bufA[i];
        #pragma unroll
        for (int o=16; o; o>>=1) sl += __shfl_xor_sync(0xffffffffu, sl, o);
        if ((lt&31)==0) red_s[lt>>5] = sl;
    }
    __syncthreads();
    // P16: cheb accumulators -> g_acc [b][tv][16] + loss finalize
    if (lt < 186) {
        int t = lt/62, v = lt%62;
        float acc[15];
        #pragma unroll
        for (int k=0;k<15;k++) acc[k]=0.f;
        float dgm1 = DgS_s[v] - 1.0f;
        for (int u=0; u<62; u++) {
            float s  = bufA[u*62+v];
            float at = bufAt[u*62+v];
            float delta = (u==v) ? 1.0f : 0.0f;
            float lt_ = dgm1*delta - s;
            float c2 = 2.0f*lt_*lt_ - delta;
            float t0 = delta*at, t1 = lt_*at, t2 = c2*at;
            const float* xr = sx + t*310 + u*5;
            #pragma unroll
            for (int f=0; f<5; f++) {
                float xv = xr[f];
                acc[f]    += t0*xv;
                acc[5+f]  += t1*xv;
                acc[10+f] += t2*xv;
            }
        }
        float4* gp = reinterpret_cast<float4*>(g_acc + (size_t)b*2976 + (size_t)(t*62+v)*16);
        gp[0] = make_float4(acc[0],acc[1],acc[2],acc[3]);
        gp[1] = make_float4(acc[4],acc[5],acc[6],acc[7]);
        gp[2] = make_float4(acc[8],acc[9],acc[10],acc[11]);
        gp[3] = make_float4(acc[12],acc[13],acc[14],0.0f);
    } else if (lt == 192) {
        float sl = 0.f;
        #pragma unroll
        for (int w=0; w<8; w++) sl += red_s[w];
        atomicAdd(out + XR_ELEMS, sl * (ALPHA/(float)NBATCH));
        float dp = 0.f;
        for (int j=0; j<62; j++) dp += DgS_s[j]*d2s_s[j];
        atomicAdd(out + XR_ELEMS + 1, dp * ALPHA);
    }
}

// ============ K3: phases 4b-6, bf16 sg, 4 blocks/SM (unchanged from R14) ============
__global__ void __launch_bounds__(512,4) stgcn_k3(
    const float* __restrict__ gx, const float* __restrict__ gTheta,
    const float* __restrict__ gtb, const float* __restrict__ grw,
    const float* __restrict__ grb, const float* __restrict__ ggamma,
    const float* __restrict__ gbeta, float* __restrict__ out)
{
    extern __shared__ float smarr[];
    const int tid = threadIdx.x;
    const int b = blockIdx.x;

    __nv_bfloat16* sgb = reinterpret_cast<__nv_bfloat16*>(smarr);  // 12288 bf16 = 6144 floats
    float* zb    = smarr + 6144;       // 4032  z [v][o] rowstride 65
    float* Th_s  = zb   + 4032;        // 960   [kf][o]
    float* x0_s  = Th_s + 960;         // 320
    float* tb_s  = x0_s + 320;         // 64
    float* rb_s  = tb_s + 64;          // 64
    float* rw_s  = rb_s + 64;          // 320
    float* gam_s = rw_s + 320;         // 64
    float* bet_s = gam_s+ 64;          // 64
    float* mu_s  = bet_s+ 64;          // 64
    float* iv_s  = mu_s + 64;          // 64

    for (int i = tid; i < 960; i += 512) Th_s[i] = gTheta[i];
    for (int i = tid; i < 310; i += 512) x0_s[i] = gx[(size_t)b*930 + i];
    for (int i = tid; i < 320; i += 512) rw_s[i] = grw[i];
    if (tid < 64) { tb_s[tid]=gtb[tid]; rb_s[tid]=grb[tid]; gam_s[tid]=ggamma[tid]; bet_s[tid]=gbeta[tid]; }
    __syncthreads();

    // Phase 4b: Theta contraction -> sg (bf16 stores)
    if (tid < 372) {
        int oh = (tid >= 186);
        int r = tid - oh*186;
        int t = r/62, v = r%62;
        int tv = t*62+v;
        const float4* ap4 = reinterpret_cast<const float4*>(g_acc + (size_t)b*2976 + (size_t)tv*16);
        float4 A0=__ldg(ap4), A1=__ldg(ap4+1), A2=__ldg(ap4+2), A3=__ldg(ap4+3);
        float a0[15] = {A0.x,A0.y,A0.z,A0.w, A1.x,A1.y,A1.z,A1.w,
                        A2.x,A2.y,A2.z,A2.w, A3.x,A3.y,A3.z};
        const float4* Th4 = reinterpret_cast<const float4*>(Th_s);  // [kf][16]
        int qb = oh*8;
        __nv_bfloat16* sgr = sgb + t*4096 + v;
        #pragma unroll 2
        for (int q=0; q<8; q++) {
            int oq = qb+q;
            float zx=0.f, zy=0.f, zz=0.f, zw=0.f;
            #pragma unroll
            for (int kf=0; kf<15; kf++) {
                float4 th = Th4[kf*16+oq];
                float av = a0[kf];
                zx += av*th.x; zy += av*th.y; zz += av*th.z; zw += av*th.w;
            }
            int o0 = oq*4;
            sgr[(o0  )*64] = __float2bfloat16(fmaxf(zx, 0.0f));
            sgr[(o0+1)*64] = __float2bfloat16(fmaxf(zy, 0.0f));
            sgr[(o0+2)*64] = __float2bfloat16(fmaxf(zz, 0.0f));
            sgr[(o0+3)*64] = __float2bfloat16(fmaxf(zw, 0.0f));
        }
    }
    for (int i = tid; i < 192; i += 512) {
        int t = i/64, c = i%64;
        sgb[t*4096 + c*64 + 62] = __float2bfloat16(0.0f);
        sgb[t*4096 + c*64 + 63] = __float2bfloat16(0.0f);
    }
    __syncthreads();

    // Phase 5: temporal conv — 4o x 2v per thread, no k-split, tw via L1
    {
        int og  = tid & 15;           // o0 = og*4
        int vg  = tid >> 4;           // 0..31, v0 = vg*2
        int o0  = og*4;
        int v0  = vg*2;
        float acc[8];                 // [vj*4+oi]
        #pragma unroll
        for (int k=0;k<8;k++) acc[k]=0.f;
        #pragma unroll 2
        for (int tc = 0; tc < 192; tc++) {
            int t = tc>>6, c = tc&63;
            __nv_bfloat162 sv2 = *reinterpret_cast<const __nv_bfloat162*>(sgb + t*4096 + c*64 + v0);
            float2 sv = __bfloat1622float2(sv2);
            float4 w0 = __ldg(reinterpret_cast<const float4*>(g_twt + (t<<12) + (c<<6) + o0));
            acc[0] += sv.x*w0.x; acc[1] += sv.x*w0.y; acc[2] += sv.x*w0.z; acc[3] += sv.x*w0.w;
            acc[4] += sv.y*w0.x; acc[5] += sv.y*w0.y; acc[6] += sv.y*w0.z; acc[7] += sv.y*w0.w;
        }
        #pragma unroll
        for (int vj=0; vj<2; vj++) {
            int v = v0+vj;
            if (v < 62) {
                const float* x0 = x0_s + v*5;
                float xa=x0[0], xb=x0[1], xc=x0[2], xd=x0[3], xe=x0[4];
                #pragma unroll
                for (int oi=0; oi<4; oi++) {
                    int o = o0+oi;
                    float tcv = (acc[vj*4+oi] + tb_s[o]) * 0.25819889f;
                    const float* rwp = rw_s + o*5;
                    float resv = rb_s[o] + xa*rwp[0]+xb*rwp[1]+xc*rwp[2]+xd*rwp[3]+xe*rwp[4];
                    zb[v*65+o] = fmaxf(resv + tcv, 0.0f);
                }
            }
        }
    }
    __syncthreads();

    // Phase 6: LayerNorm + writeback
    {
        int v = tid>>3, g = tid&7;
        bool act = (v < 62);
        float s = 0.f;
        if (act) for (int o=g; o<64; o+=8) s += zb[v*65+o];
        #pragma unroll
        for (int o=4; o; o>>=1) s += __shfl_xor_sync(0xffffffffu, s, o);
        float mu = s * (1.0f/64.0f);
        float vv = 0.f;
        if (act) for (int o=g; o<64; o+=8) { float d = zb[v*65+o]-mu; vv += d*d; }
        #pragma unroll
        for (int o=4; o; o>>=1) vv += __shfl_xor_sync(0xffffffffu, vv, o);
        vv *= (1.0f/64.0f);
        if (act && g==0) { mu_s[v] = mu; iv_s[v] = rsqrtf(vv + LN_EPS); }
    }
    __syncthreads();
    for (int i = tid; i < 3968; i += 512) {
        int v = i>>6, o = i&63;
        float val = (zb[v*65+o]-mu_s[v])*iv_s[v]*gam_s[o] + bet_s[o];
        out[(size_t)b*3968 + i] = val;
    }
}

#define SMEM_A_BYTES (9344*4)
#define SMEM_K3_BYTES (12160*4)

extern "C" void kernel_launch(void* const* d_in, const int* in_sizes, int n_in,
                              void* d_out, int out_size) {
    const float* x     = (const float*)d_in[0];
    const float* U1    = (const float*)d_in[1];
    const float* U2    = (const float*)d_in[2];
    const float* U3    = (const float*)d_in[3];
    const float* be    = (const float*)d_in[4];
    const float* Ve    = (const float*)d_in[5];
    const float* W1    = (const float*)d_in[6];
    const float* W2    = (const float*)d_in[7];
    const float* W3    = (const float*)d_in[8];
    const float* bs    = (const float*)d_in[9];
    const float* Vs    = (const float*)d_in[10];
    const float* a     = (const float*)d_in[11];
    const float* Theta = (const float*)d_in[12];
    const float* tw    = (const float*)d_in[13];
    const float* tb    = (const float*)d_in[14];
    const float* rw    = (const float*)d_in[15];
    const float* rb    = (const float*)d_in[16];
    const float* gamma = (const float*)d_in[17];
    const float* beta  = (const float*)d_in[18];
    float* out = (float*)d_out;

    cudaFuncSetAttribute(stgcn_a,  cudaFuncAttributeMaxDynamicSharedMemorySize, SMEM_A_BYTES);
    cudaFuncSetAttribute(stgcn_k3, cudaFuncAttributeMaxDynamicSharedMemorySize, SMEM_K3_BYTES);

    prep_kernel<<<48, 256>>>(tw, out);
    stgcn_a<<<NBATCH, 256, SMEM_A_BYTES>>>(x, U1, U2, U3, be, Ve, W1, W2, W3,
                                           bs, Vs, a, out);
    stgcn_k3<<<NBATCH, 512, SMEM_K3_BYTES>>>(x, Theta, tb, rw, rb, gamma, beta, out);
}

// round 16
// speedup vs baseline: 2.4396x; 1.3876x over previous
#include <cuda_runtime.h>
#include <cuda_bf16.h>
#include <math.h>

#define NBATCH 2048
#define ALPHA 1e-4f
#define LN_EPS 1e-5f

#define XR_ELEMS (NBATCH*62*64)      /* 8126464 */
#define S_BASE   (XR_ELEMS + 2)

// Scratch: per-batch cheb accumulators [b][tv][16], bf16 tw as A-operand [o][k], k=t*64+c.
__device__ float g_acc[NBATCH*2976];
__device__ __nv_bfloat16 g_twb[12288];   // [o][k] k-major, k = t*64+c (192 per row)

__device__ __forceinline__ float fsig(float x){ return __fdividef(1.0f, 1.0f+__expf(-x)); }

__device__ __forceinline__ void mma_bf16(float* d, unsigned a0, unsigned a1, unsigned a2, unsigned a3,
                                         unsigned b0, unsigned b1) {
    asm volatile("mma.sync.aligned.m16n8k16.row.col.f32.bf16.bf16.f32 "
                 "{%0,%1,%2,%3}, {%4,%5,%6,%7}, {%8,%9}, {%0,%1,%2,%3};"
                 : "+f"(d[0]), "+f"(d[1]), "+f"(d[2]), "+f"(d[3])
                 : "r"(a0), "r"(a1), "r"(a2), "r"(a3), "r"(b0), "r"(b1));
}

__global__ void prep_kernel(const float* __restrict__ gtw, float* __restrict__ out) {
    int i = blockIdx.x*256 + threadIdx.x;
    if (i < 12288) {
        // gtw layout: [o][c][t] (o*192 + c*3 + t). Write [o][t*64+c].
        int o = i/192, c = (i%192)/3, t = i%3;
        g_twb[o*192 + t*64 + c] = __float2bfloat16(gtw[i]);
    }
    if (i < 2) out[XR_ELEMS + i] = 0.0f;
}

// ============ KERNEL A: phases 0-4a, 256 threads, 6 blocks/SM (aliased smem) ============
__global__ void __launch_bounds__(256,6) stgcn_a(
    const float* __restrict__ gx, const float* __restrict__ gU1,
    const float* __restrict__ gU2, const float* __restrict__ gU3,
    const float* __restrict__ gbe, const float* __restrict__ gVe,
    const float* __restrict__ gW1, const float* __restrict__ gW2,
    const float* __restrict__ gW3, const float* __restrict__ gbs,
    const float* __restrict__ gVs, const float* __restrict__ ga,
    float* __restrict__ out)
{
    extern __shared__ float smarr[];
    const int lt = threadIdx.x;
    const int b  = blockIdx.x;

    float* sx    = smarr;            // 936
    float* bufA  = sx   + 936;       // 3968
    float* bufAt = bufA + 3968;      // 3844
    float* slhs_s= bufAt+ 3844;      // 188
    float* srhs_s= slhs_s+188;       // 188
    float* colsum= srhs_s+188;       // 64
    float* DgS_s = colsum+ 64;       // 64
    float* d2s_s = DgS_s + 64;       // 64
    float* red_s = d2s_s + 64;       // 8
    float* a_s   = red_s + 8;        // 8
    float* sxT   = bufA;
    float* y_s   = bufAt + 0;
    float* lhs_s = bufAt + 16;
    float* rhs_s = bufAt + 204;
    float* prod_s= bufAt + 392;
    float* E_s   = bufAt + 404;
    float* At_s  = bufAt + 416;
    float* U2_s  = bufAt + 428;
    float* U1_s  = bufAt + 740;
    float* U3_s  = bufAt + 804;
    float* be_s  = bufAt + 812;
    float* Ve_s  = bufAt + 824;
    float* W1_s  = bufAt + 836;
    float* W2_s  = bufAt + 840;
    float* W3_s  = bufAt + 856;

    for (int i = lt; i < 930; i += 256) sx[i] = gx[(size_t)b*930 + i];
    if (lt >= 128 && lt < 128+155) {
        U2_s[(lt-128)*2]   = gU2[(lt-128)*2];
        U2_s[(lt-128)*2+1] = gU2[(lt-128)*2+1];
    }
    if (lt < 62) U1_s[lt] = gU1[lt];
    else if (lt >= 64 && lt < 69)  U3_s[lt-64] = gU3[lt-64];
    else if (lt >= 70 && lt < 79)  be_s[lt-70] = gbe[lt-70];
    else if (lt >= 80 && lt < 89)  Ve_s[lt-80] = gVe[lt-80];
    else if (lt >= 90 && lt < 93)  W1_s[lt-90] = gW1[lt-90];
    else if (lt >= 96 && lt < 111) W2_s[lt-96] = gW2[lt-96];
    else if (lt >= 112 && lt < 117) W3_s[lt-112] = gW3[lt-112];
    else if (lt >= 118 && lt < 123) a_s[lt-118] = ga[lt-118];
    __syncthreads();

    if (lt < 15) {
        int t = lt/5, f = lt%5;
        float s = 0.f;
        for (int v = 0; v < 62; v++) s += sx[t*310+v*5+f]*U1_s[v];
        y_s[t*5+f] = s;
    }
    if (lt >= 32 && lt < 218) {
        int r = lt-32;
        int v = r/3, t = r%3;
        const float* xr = sx + t*310 + v*5;
        float s = 0.f;
        #pragma unroll
        for (int f=0; f<5; f++) s += U3_s[f]*xr[f];
        rhs_s[v*3+t] = s;
    }
    __syncthreads();
    if (lt < 186) {
        int t = lt/62, u = lt%62;
        float s = 0.f;
        #pragma unroll
        for (int f=0; f<5; f++) s += y_s[t*5+f]*U2_s[f*62+u];
        lhs_s[t*62+u] = s;
    }
    __syncthreads();
    if (lt < 9) {
        int t = lt/3, u = lt%3;
        float s = 0.f;
        for (int v=0; v<62; v++) s += lhs_s[t*62+v]*rhs_s[v*3+u];
        prod_s[t*3+u] = s;
    }
    __syncthreads();
    if (lt < 9) {
        int t = lt/3, u = lt%3;
        float s = 0.f;
        #pragma unroll
        for (int k=0; k<3; k++) s += Ve_s[t*3+k]*fsig(prod_s[k*3+u]+be_s[k*3+u]);
        E_s[t*3+u] = s;
    }
    __syncthreads();
    if (lt < 3) {
        int u = lt;
        float m = fmaxf(E_s[u], fmaxf(E_s[3+u], E_s[6+u]));
        float e0=__expf(E_s[u]-m), e1=__expf(E_s[3+u]-m), e2=__expf(E_s[6+u]-m);
        float inv = __fdividef(1.0f, e0+e1+e2);
        At_s[u]=e0*inv; At_s[3+u]=e1*inv; At_s[6+u]=e2*inv;
    }
    __syncthreads();
    for (int i = lt; i < 930; i += 256) {
        int u = i/310, r = i%310;
        sxT[i] = (sx[r]*At_s[u] + sx[310+r]*At_s[3+u] + sx[620+r]*At_s[6+u]) * 0.056796183f;
    }
    __syncthreads();
    if (lt < 186) {
        int v = lt/3, s = lt%3;
        float acc = 0.f;
        #pragma unroll
        for (int f=0; f<5; f++) {
            float yv = sxT[v*5+f]*W1_s[0] + sxT[310+v*5+f]*W1_s[1] + sxT[620+v*5+f]*W1_s[2];
            acc += yv*W2_s[f*3+s];
        }
        slhs_s[v*3+s] = acc;
        int t = lt/62, vv = lt%62;
        const float* xr = sxT + t*310 + vv*5;
        float s2 = 0.f;
        #pragma unroll
        for (int f=0; f<5; f++) s2 += W3_s[f]*xr[f];
        srhs_s[t*62+vv] = s2;
    }
    __syncthreads();
    for (int i = lt; i < 3844; i += 256) {
        int w = i/62, v = i%62;
        float p = slhs_s[w*3]*srhs_s[v] + slhs_s[w*3+1]*srhs_s[62+v]
                + slhs_s[w*3+2]*srhs_s[124+v] + gbs[i];
        bufA[w*64+v] = fsig(p);
    }
    if (lt < 62) { bufA[lt*64+62]=0.f; bufA[lt*64+63]=0.f; }
    __syncthreads();
    {
        int u2 = lt>>3;
        int vq = lt&7;
        int u0 = u2*2;
        if (u0 < 62) {
            float acc[16];
            #pragma unroll
            for (int k=0;k<16;k++) acc[k]=0.f;
            const float* va_p = gVs + u0*62;
            const float* vb_p = va_p + 62;
            for (int w=0; w<62; w++) {
                float va = __ldg(va_p + w);
                float vb = __ldg(vb_p + w);
                const float4* rowp = reinterpret_cast<const float4*>(bufA + w*64 + vq*8);
                float4 s0 = rowp[0], s1 = rowp[1];
                float sv[8] = {s0.x,s0.y,s0.z,s0.w,s1.x,s1.y,s1.z,s1.w};
                #pragma unroll
                for (int j=0;j<8;j++) { acc[j] += va*sv[j]; acc[8+j] += vb*sv[j]; }
            }
            #pragma unroll
            for (int j=0;j<8;j++) {
                int v = vq*8+j;
                if (v < 62) {
                    bufAt[u0*62+v]     = acc[j];
                    bufAt[(u0+1)*62+v] = acc[8+j];
                }
            }
        }
    }
    __syncthreads();
    {
        int v = lt>>2, g = lt&3;
        bool act = (v < 62);
        float m = -1e30f;
        if (act) for (int u=g; u<62; u+=4) m = fmaxf(m, bufAt[u*62+v]);
        m = fmaxf(m, __shfl_xor_sync(0xffffffffu, m, 1));
        m = fmaxf(m, __shfl_xor_sync(0xffffffffu, m, 2));
        float ssum = 0.f;
        if (act) for (int u=g; u<62; u+=4) { float e = __expf(bufAt[u*62+v]-m); bufAt[u*62+v]=e; ssum+=e; }
        ssum += __shfl_xor_sync(0xffffffffu, ssum, 1);
        ssum += __shfl_xor_sync(0xffffffffu, ssum, 2);
        float inv = __fdividef(1.0f, ssum);
        if (act) for (int u=g; u<62; u+=4) bufAt[u*62+v] *= inv;
    }
    __syncthreads();
    const float* xm = sx + 310;
    {
        float a0=a_s[0],a1=a_s[1],a2=a_s[2],a3=a_s[3],a4=a_s[4];
        for (int i = lt; i < 3844; i += 256) {
            int ii = i/62, jj = i%62;
            const float* xi = xm + ii*5; const float* xj = xm + jj*5;
            float e = fabsf(xi[0]-xj[0])*a0 + fabsf(xi[1]-xj[1])*a1 + fabsf(xi[2]-xj[2])*a2
                    + fabsf(xi[3]-xj[3])*a3 + fabsf(xi[4]-xj[4])*a4;
            bufA[i] = __expf(fmaxf(e, 0.0f));
        }
    }
    __syncthreads();
    {
        int j = lt>>2, g = lt&3;
        bool act = (j < 62);
        float cs = 0.f;
        if (act) for (int i=g; i<62; i+=4) cs += bufA[i*62+j];
        cs += __shfl_xor_sync(0xffffffffu, cs, 1);
        cs += __shfl_xor_sync(0xffffffffu, cs, 2);
        if (act && g==0) colsum[j] = __fdividef(1.0f, cs);
    }
    __syncthreads();
    for (int i = lt; i < 3844; i += 256) {
        float s = bufA[i] * colsum[i%62];
        bufA[i] = s;
        out[S_BASE + (size_t)b*3844 + i] = s;
    }
    __syncthreads();
    {
        int j = lt>>2, g = lt&3;
        bool act = (j < 62);
        float cs = 0.f, dd = 0.f;
        if (act) {
            const float* xj = xm + j*5;
            for (int i=g; i<62; i+=4) {
                cs += bufA[i*62+j];
                const float* xi = xm + i*5;
                #pragma unroll
                for (int f=0; f<5; f++) { float d = xj[f]-xi[f]; dd += d*d; }
            }
        }
        cs += __shfl_xor_sync(0xffffffffu, cs, 1);
        cs += __shfl_xor_sync(0xffffffffu, cs, 2);
        dd += __shfl_xor_sync(0xffffffffu, dd, 1);
        dd += __shfl_xor_sync(0xffffffffu, dd, 2);
        if (act && g==0) { DgS_s[j] = cs; d2s_s[j] = dd; }
    }
    __syncthreads();
    {
        float sl = 0.f;
        for (int i = lt; i < 3844; i += 256) sl += bufA[i]*bufA[i];
        #pragma unroll
        for (int o=16; o; o>>=1) sl += __shfl_xor_sync(0xffffffffu, sl, o);
        if ((lt&31)==0) red_s[lt>>5] = sl;
    }
    __syncthreads();
    if (lt < 186) {
        int t = lt/62, v = lt%62;
        float acc[15];
        #pragma unroll
        for (int k=0;k<15;k++) acc[k]=0.f;
        float dgm1 = DgS_s[v] - 1.0f;
        for (int u=0; u<62; u++) {
            float s  = bufA[u*62+v];
            float at = bufAt[u*62+v];
            float delta = (u==v) ? 1.0f : 0.0f;
            float lt_ = dgm1*delta - s;
            float c2 = 2.0f*lt_*lt_ - delta;
            float t0 = delta*at, t1 = lt_*at, t2 = c2*at;
            const float* xr = sx + t*310 + u*5;
            #pragma unroll
            for (int f=0; f<5; f++) {
                float xv = xr[f];
                acc[f]    += t0*xv;
                acc[5+f]  += t1*xv;
                acc[10+f] += t2*xv;
            }
        }
        float4* gp = reinterpret_cast<float4*>(g_acc + (size_t)b*2976 + (size_t)(t*62+v)*16);
        gp[0] = make_float4(acc[0],acc[1],acc[2],acc[3]);
        gp[1] = make_float4(acc[4],acc[5],acc[6],acc[7]);
        gp[2] = make_float4(acc[8],acc[9],acc[10],acc[11]);
        gp[3] = make_float4(acc[12],acc[13],acc[14],0.0f);
    } else if (lt == 192) {
        float sl = 0.f;
        #pragma unroll
        for (int w=0; w<8; w++) sl += red_s[w];
        atomicAdd(out + XR_ELEMS, sl * (ALPHA/(float)NBATCH));
        float dp = 0.f;
        for (int j=0; j<62; j++) dp += DgS_s[j]*d2s_s[j];
        atomicAdd(out + XR_ELEMS + 1, dp * ALPHA);
    }
}

// ============ K3: 4b -> mma.sync temporal conv -> LN; bf16 sg [v][k] rowstride 200 ============
__global__ void __launch_bounds__(512,4) stgcn_k3(
    const float* __restrict__ gx, const float* __restrict__ gTheta,
    const float* __restrict__ gtb, const float* __restrict__ grw,
    const float* __restrict__ grb, const float* __restrict__ ggamma,
    const float* __restrict__ gbeta, float* __restrict__ out)
{
    extern __shared__ float smarr[];
    const int tid = threadIdx.x;
    const int b = blockIdx.x;

    __nv_bfloat16* sgb = reinterpret_cast<__nv_bfloat16*>(smarr);  // [v<64][k<200] bf16 = 12800 = 6400 floats
    float* zb    = smarr + 6400;       // 4032  z [v][o] rowstride 65
    float* Th_s  = zb   + 4032;        // 960   [kf][o]
    float* x0_s  = Th_s + 960;         // 320
    float* tb_s  = x0_s + 320;         // 64
    float* rb_s  = tb_s + 64;          // 64
    float* rw_s  = rb_s + 64;          // 320
    float* gam_s = rw_s + 320;         // 64
    float* bet_s = gam_s+ 64;          // 64
    float* mu_s  = bet_s+ 64;          // 64
    float* iv_s  = mu_s + 64;          // 64

    for (int i = tid; i < 960; i += 512) Th_s[i] = gTheta[i];
    for (int i = tid; i < 310; i += 512) x0_s[i] = gx[(size_t)b*930 + i];
    for (int i = tid; i < 320; i += 512) rw_s[i] = grw[i];
    if (tid < 64) { tb_s[tid]=gtb[tid]; rb_s[tid]=grb[tid]; gam_s[tid]=ggamma[tid]; bet_s[tid]=gbeta[tid]; }
    __syncthreads();

    // Phase 4b: Theta contraction -> sgb[v][k], k = t*64+c (thread covers c = oh*32..+32)
    if (tid < 372) {
        int oh = (tid >= 186);
        int r = tid - oh*186;
        int t = r/62, v = r%62;
        int tv = t*62+v;
        const float4* ap4 = reinterpret_cast<const float4*>(g_acc + (size_t)b*2976 + (size_t)tv*16);
        float4 A0=__ldg(ap4), A1=__ldg(ap4+1), A2=__ldg(ap4+2), A3=__ldg(ap4+3);
        float a0[15] = {A0.x,A0.y,A0.z,A0.w, A1.x,A1.y,A1.z,A1.w,
                        A2.x,A2.y,A2.z,A2.w, A3.x,A3.y,A3.z};
        const float4* Th4 = reinterpret_cast<const float4*>(Th_s);  // [kf][16] float4
        int qb = oh*8;
        __nv_bfloat16* sgr = sgb + v*200 + t*64;   // + c
        #pragma unroll 2
        for (int q=0; q<8; q++) {
            int oq = qb+q;
            float zx=0.f, zy=0.f, zz=0.f, zw=0.f;
            #pragma unroll
            for (int kf=0; kf<15; kf++) {
                float4 th = Th4[kf*16+oq];
                float av = a0[kf];
                zx += av*th.x; zy += av*th.y; zz += av*th.z; zw += av*th.w;
            }
            int c0 = oq*4;   // global c = oh*32 + q*4 .. +3 (oq = oh*8+q)
            __nv_bfloat162 p0; p0.x = __float2bfloat16(fmaxf(zx,0.f)); p0.y = __float2bfloat16(fmaxf(zy,0.f));
            __nv_bfloat162 p1; p1.x = __float2bfloat16(fmaxf(zz,0.f)); p1.y = __float2bfloat16(fmaxf(zw,0.f));
            *reinterpret_cast<__nv_bfloat162*>(sgr + c0)     = p0;
            *reinterpret_cast<__nv_bfloat162*>(sgr + c0 + 2) = p1;
        }
    }
    // zero pad rows v=62,63 over k=0..191
    for (int i = tid; i < 384; i += 512) {
        int v = 62 + i/192, k = i%192;
        sgb[v*200 + k] = __float2bfloat16(0.0f);
    }
    __syncthreads();

    // Phase 5: D[o][v] = sum_k W[o][k] * SG[k][v] via mma.sync m16n8k16 bf16
    // 16 warps: m = w&3 (o-tile of 16), n-pair = w>>2 (two 8-wide v-tiles)
    {
        int lane = tid & 31, w = tid >> 5;
        int m  = w & 3;
        int n0 = (w >> 2)*2, n1 = n0 + 1;
        int gr  = lane >> 2;         // A row / B col / D row offset
        int gc2 = (lane & 3)*2;      // A k-offset / B k-offset / D col offset
        float d0[4] = {0.f,0.f,0.f,0.f};
        float d1[4] = {0.f,0.f,0.f,0.f};
        const __nv_bfloat16* Abase = g_twb + (m*16 + gr)*192 + gc2;
        const __nv_bfloat16* B0 = sgb + (n0*8 + gr)*200 + gc2;
        const __nv_bfloat16* B1 = sgb + (n1*8 + gr)*200 + gc2;
        #pragma unroll
        for (int kt = 0; kt < 12; kt++) {
            int k0 = kt*16;
            unsigned a0 = *reinterpret_cast<const unsigned*>(Abase + k0);
            unsigned a1 = *reinterpret_cast<const unsigned*>(Abase + 8*192 + k0);
            unsigned a2 = *reinterpret_cast<const unsigned*>(Abase + k0 + 8);
            unsigned a3 = *reinterpret_cast<const unsigned*>(Abase + 8*192 + k0 + 8);
            unsigned b00 = *reinterpret_cast<const unsigned*>(B0 + k0);
            unsigned b01 = *reinterpret_cast<const unsigned*>(B0 + k0 + 8);
            unsigned b10 = *reinterpret_cast<const unsigned*>(B1 + k0);
            unsigned b11 = *reinterpret_cast<const unsigned*>(B1 + k0 + 8);
            mma_bf16(d0, a0, a1, a2, a3, b00, b01);
            mma_bf16(d1, a0, a1, a2, a3, b10, b11);
        }
        // Epilogue: tb + scale + residual + relu -> zb[v][o]
        int oA = m*16 + gr, oB = oA + 8;
        #pragma unroll
        for (int ti = 0; ti < 2; ti++) {
            float* d = ti ? d1 : d0;
            int vbase = (ti ? n1 : n0)*8 + gc2;
            #pragma unroll
            for (int e = 0; e < 4; e++) {
                int o = (e >= 2) ? oB : oA;
                int v = vbase + (e & 1);
                if (v < 62) {
                    float tcv = (d[e] + tb_s[o]) * 0.25819889f;
                    const float* x0 = x0_s + v*5;
                    const float* rwp = rw_s + o*5;
                    float resv = rb_s[o] + x0[0]*rwp[0]+x0[1]*rwp[1]+x0[2]*rwp[2]
                               + x0[3]*rwp[3]+x0[4]*rwp[4];
                    zb[v*65+o] = fmaxf(resv + tcv, 0.0f);
                }
            }
        }
    }
    __syncthreads();

    // Phase 6: LayerNorm + writeback
    {
        int v = tid>>3, g = tid&7;
        bool act = (v < 62);
        float s = 0.f;
        if (act) for (int o=g; o<64; o+=8) s += zb[v*65+o];
        #pragma unroll
        for (int o=4; o; o>>=1) s += __shfl_xor_sync(0xffffffffu, s, o);
        float mu = s * (1.0f/64.0f);
        float vv = 0.f;
        if (act) for (int o=g; o<64; o+=8) { float d = zb[v*65+o]-mu; vv += d*d; }
        #pragma unroll
        for (int o=4; o; o>>=1) vv += __shfl_xor_sync(0xffffffffu, vv, o);
        vv *= (1.0f/64.0f);
        if (act && g==0) { mu_s[v] = mu; iv_s[v] = rsqrtf(vv + LN_EPS); }
    }
    __syncthreads();
    for (int i = tid; i < 3968; i += 512) {
        int v = i>>6, o = i&63;
        float val = (zb[v*65+o]-mu_s[v])*iv_s[v]*gam_s[o] + bet_s[o];
        out[(size_t)b*3968 + i] = val;
    }
}

#define SMEM_A_BYTES (9344*4)
#define SMEM_K3_BYTES (12416*4)

extern "C" void kernel_launch(void* const* d_in, const int* in_sizes, int n_in,
                              void* d_out, int out_size) {
    const float* x     = (const float*)d_in[0];
    const float* U1    = (const float*)d_in[1];
    const float* U2    = (const float*)d_in[2];
    const float* U3    = (const float*)d_in[3];
    const float* be    = (const float*)d_in[4];
    const float* Ve    = (const float*)d_in[5];
    const float* W1    = (const float*)d_in[6];
    const float* W2    = (const float*)d_in[7];
    const float* W3    = (const float*)d_in[8];
    const float* bs    = (const float*)d_in[9];
    const float* Vs    = (const float*)d_in[10];
    const float* a     = (const float*)d_in[11];
    const float* Theta = (const float*)d_in[12];
    const float* tw    = (const float*)d_in[13];
    const float* tb    = (const float*)d_in[14];
    const float* rw    = (const float*)d_in[15];
    const float* rb    = (const float*)d_in[16];
    const float* gamma = (const float*)d_in[17];
    const float* beta  = (const float*)d_in[18];
    float* out = (float*)d_out;

    cudaFuncSetAttribute(stgcn_a,  cudaFuncAttributeMaxDynamicSharedMemorySize, SMEM_A_BYTES);
    cudaFuncSetAttribute(stgcn_k3, cudaFuncAttributeMaxDynamicSharedMemorySize, SMEM_K3_BYTES);

    prep_kernel<<<48, 256>>>(tw, out);
    stgcn_a<<<NBATCH, 256, SMEM_A_BYTES>>>(x, U1, U2, U3, be, Ve, W1, W2, W3,
                                           bs, Vs, a, out);
    stgcn_k3<<<NBATCH, 512, SMEM_K3_BYTES>>>(x, Theta, tb, rw, rb, gamma, beta, out);
}

// round 17
// speedup vs baseline: 2.8467x; 1.1669x over previous
#include <cuda_runtime.h>
#include <cuda_bf16.h>
#include <math.h>

#define NBATCH 2048
#define ALPHA 1e-4f
#define LN_EPS 1e-5f

#define XR_ELEMS (NBATCH*62*64)      /* 8126464 */
#define S_BASE   (XR_ELEMS + 2)

// Scratch: per-batch cheb accumulators [b][tv][16]; bf16 tw [o][k]; bf16 Vs [u][w] 64x64.
__device__ float g_acc[NBATCH*2976];
__device__ __nv_bfloat16 g_twb[12288];   // [o][k] k-major, k = t*64+c (192 per row)
__device__ __nv_bfloat16 g_vsb[4096];    // [u][w] row-major 64x64, zero-padded

__device__ __forceinline__ float fsig(float x){ return __fdividef(1.0f, 1.0f+__expf(-x)); }

__device__ __forceinline__ void mma_bf16(float* d, unsigned a0, unsigned a1, unsigned a2, unsigned a3,
                                         unsigned b0, unsigned b1) {
    asm volatile("mma.sync.aligned.m16n8k16.row.col.f32.bf16.bf16.f32 "
                 "{%0,%1,%2,%3}, {%4,%5,%6,%7}, {%8,%9}, {%0,%1,%2,%3};"
                 : "+f"(d[0]), "+f"(d[1]), "+f"(d[2]), "+f"(d[3])
                 : "r"(a0), "r"(a1), "r"(a2), "r"(a3), "r"(b0), "r"(b1));
}

__global__ void prep_kernel(const float* __restrict__ gtw, const float* __restrict__ gVs,
                            float* __restrict__ out) {
    int i = blockIdx.x*256 + threadIdx.x;
    if (i < 12288) {
        int o = i/192, c = (i%192)/3, t = i%3;
        g_twb[o*192 + t*64 + c] = __float2bfloat16(gtw[i]);
    }
    if (i < 4096) {
        int u = i>>6, w = i&63;
        g_vsb[i] = (u < 62 && w < 62) ? __float2bfloat16(gVs[u*62+w]) : __float2bfloat16(0.0f);
    }
    if (i < 2) out[XR_ELEMS + i] = 0.0f;
}

// ============ KERNEL A: phases 0-4a, 256 threads, 6 blocks/SM (aliased smem) ============
__global__ void __launch_bounds__(256,6) stgcn_a(
    const float* __restrict__ gx, const float* __restrict__ gU1,
    const float* __restrict__ gU2, const float* __restrict__ gU3,
    const float* __restrict__ gbe, const float* __restrict__ gVe,
    const float* __restrict__ gW1, const float* __restrict__ gW2,
    const float* __restrict__ gW3, const float* __restrict__ gbs,
    const float* __restrict__ ga, float* __restrict__ out)
{
    extern __shared__ float smarr[];
    const int lt = threadIdx.x;
    const int b  = blockIdx.x;

    float* sx    = smarr;            // 936
    float* bufA  = sx   + 936;       // 3968 : sxT (P6-P7) -> sigT bf16 (P8-P9) -> tmpS/S (P11+)
    float* bufAt = bufA + 3968;      // 3844 : early temporaries -> Sm/spatial_At (P9+)
    float* slhs_s= bufAt+ 3844;      // 188
    float* srhs_s= slhs_s+188;       // 188
    float* colsum= srhs_s+188;       // 64
    float* DgS_s = colsum+ 64;       // 64
    float* d2s_s = DgS_s + 64;       // 64
    float* red_s = d2s_s + 64;       // 8
    float* a_s   = red_s + 8;        // 8
    float* sxT   = bufA;
    __nv_bfloat16* sigT = reinterpret_cast<__nv_bfloat16*>(bufA);  // [v<64][w<72] bf16 (4608 = 2304 floats)
    float* y_s   = bufAt + 0;
    float* lhs_s = bufAt + 16;
    float* rhs_s = bufAt + 204;
    float* prod_s= bufAt + 392;
    float* E_s   = bufAt + 404;
    float* At_s  = bufAt + 416;
    float* U2_s  = bufAt + 428;
    float* U1_s  = bufAt + 740;
    float* U3_s  = bufAt + 804;
    float* be_s  = bufAt + 812;
    float* Ve_s  = bufAt + 824;
    float* W1_s  = bufAt + 836;
    float* W2_s  = bufAt + 840;
    float* W3_s  = bufAt + 856;

    for (int i = lt; i < 930; i += 256) sx[i] = gx[(size_t)b*930 + i];
    if (lt >= 128 && lt < 128+155) {
        U2_s[(lt-128)*2]   = gU2[(lt-128)*2];
        U2_s[(lt-128)*2+1] = gU2[(lt-128)*2+1];
    }
    if (lt < 62) U1_s[lt] = gU1[lt];
    else if (lt >= 64 && lt < 69)  U3_s[lt-64] = gU3[lt-64];
    else if (lt >= 70 && lt < 79)  be_s[lt-70] = gbe[lt-70];
    else if (lt >= 80 && lt < 89)  Ve_s[lt-80] = gVe[lt-80];
    else if (lt >= 90 && lt < 93)  W1_s[lt-90] = gW1[lt-90];
    else if (lt >= 96 && lt < 111) W2_s[lt-96] = gW2[lt-96];
    else if (lt >= 112 && lt < 117) W3_s[lt-112] = gW3[lt-112];
    else if (lt >= 118 && lt < 123) a_s[lt-118] = ga[lt-118];
    __syncthreads();

    // P1: y + rhs
    if (lt < 15) {
        int t = lt/5, f = lt%5;
        float s = 0.f;
        for (int v = 0; v < 62; v++) s += sx[t*310+v*5+f]*U1_s[v];
        y_s[t*5+f] = s;
    }
    if (lt >= 32 && lt < 218) {
        int r = lt-32;
        int v = r/3, t = r%3;
        const float* xr = sx + t*310 + v*5;
        float s = 0.f;
        #pragma unroll
        for (int f=0; f<5; f++) s += U3_s[f]*xr[f];
        rhs_s[v*3+t] = s;
    }
    __syncthreads();
    // P2: lhs
    if (lt < 186) {
        int t = lt/62, u = lt%62;
        float s = 0.f;
        #pragma unroll
        for (int f=0; f<5; f++) s += y_s[t*5+f]*U2_s[f*62+u];
        lhs_s[t*62+u] = s;
    }
    __syncthreads();
    // P3: prod
    if (lt < 9) {
        int t = lt/3, u = lt%3;
        float s = 0.f;
        for (int v=0; v<62; v++) s += lhs_s[t*62+v]*rhs_s[v*3+u];
        prod_s[t*3+u] = s;
    }
    __syncthreads();
    // P4: E
    if (lt < 9) {
        int t = lt/3, u = lt%3;
        float s = 0.f;
        #pragma unroll
        for (int k=0; k<3; k++) s += Ve_s[t*3+k]*fsig(prod_s[k*3+u]+be_s[k*3+u]);
        E_s[t*3+u] = s;
    }
    __syncthreads();
    // P5: softmax over t
    if (lt < 3) {
        int u = lt;
        float m = fmaxf(E_s[u], fmaxf(E_s[3+u], E_s[6+u]));
        float e0=__expf(E_s[u]-m), e1=__expf(E_s[3+u]-m), e2=__expf(E_s[6+u]-m);
        float inv = __fdividef(1.0f, e0+e1+e2);
        At_s[u]=e0*inv; At_s[3+u]=e1*inv; At_s[6+u]=e2*inv;
    }
    __syncthreads();
    // P6: x_TAt
    for (int i = lt; i < 930; i += 256) {
        int u = i/310, r = i%310;
        sxT[i] = (sx[r]*At_s[u] + sx[310+r]*At_s[3+u] + sx[620+r]*At_s[6+u]) * 0.056796183f;
    }
    __syncthreads();
    // P7: slhs + srhs
    if (lt < 186) {
        int v = lt/3, s = lt%3;
        float acc = 0.f;
        #pragma unroll
        for (int f=0; f<5; f++) {
            float yv = sxT[v*5+f]*W1_s[0] + sxT[310+v*5+f]*W1_s[1] + sxT[620+v*5+f]*W1_s[2];
            acc += yv*W2_s[f*3+s];
        }
        slhs_s[v*3+s] = acc;
        int t = lt/62, vv = lt%62;
        const float* xr = sxT + t*310 + vv*5;
        float s2 = 0.f;
        #pragma unroll
        for (int f=0; f<5; f++) s2 += W3_s[f]*xr[f];
        srhs_s[t*62+vv] = s2;
    }
    __syncthreads();
    // P8: sigmoid -> sigT bf16 [v][w] rowstride 72 (overwrites sxT region)
    for (int i = lt; i < 3844; i += 256) {
        int w = i/62, v = i%62;
        float p = slhs_s[w*3]*srhs_s[v] + slhs_s[w*3+1]*srhs_s[62+v]
                + slhs_s[w*3+2]*srhs_s[124+v] + gbs[i];
        sigT[v*72+w] = __float2bfloat16(fsig(p));
    }
    if (lt < 128) {                               // pad w=62,63 for all v<64
        int v = lt>>1, w = 62+(lt&1);
        sigT[v*72+w] = __float2bfloat16(0.0f);
    } else {                                      // pad rows v=62,63 (w 0..63)
        int r = lt-128, v = 62+(r>>6), w = r&63;
        sigT[v*72+w] = __float2bfloat16(0.0f);
    }
    __syncthreads();
    // P9: Sm = Vs @ sig via mma.sync m16n8k16 (8 warps: m=w&3, 4 n-tiles each)
    {
        int lane = lt & 31, w = lt >> 5;
        int m  = w & 3;
        int nb = (w >> 2)*4;          // n-tiles nb..nb+3
        int gr  = lane >> 2;
        int gc2 = (lane & 3)*2;
        const __nv_bfloat16* Abase = g_vsb + (m*16 + gr)*64 + gc2;
        unsigned a[4][4];
        #pragma unroll
        for (int kt = 0; kt < 4; kt++) {
            int k0 = kt*16;
            a[kt][0] = *reinterpret_cast<const unsigned*>(Abase + k0);
            a[kt][1] = *reinterpret_cast<const unsigned*>(Abase + 8*64 + k0);
            a[kt][2] = *reinterpret_cast<const unsigned*>(Abase + k0 + 8);
            a[kt][3] = *reinterpret_cast<const unsigned*>(Abase + 8*64 + k0 + 8);
        }
        int uA = m*16 + gr, uB = uA + 8;
        #pragma unroll
        for (int nt = 0; nt < 4; nt++) {
            int n = nb + nt;
            const __nv_bfloat16* B0 = sigT + (n*8 + gr)*72 + gc2;
            float d[4] = {0.f,0.f,0.f,0.f};
            #pragma unroll
            for (int kt = 0; kt < 4; kt++) {
                int k0 = kt*16;
                unsigned b0 = *reinterpret_cast<const unsigned*>(B0 + k0);
                unsigned b1 = *reinterpret_cast<const unsigned*>(B0 + k0 + 8);
                mma_bf16(d, a[kt][0], a[kt][1], a[kt][2], a[kt][3], b0, b1);
            }
            int vb = n*8 + gc2;
            #pragma unroll
            for (int e = 0; e < 4; e++) {
                int u = (e >= 2) ? uB : uA;
                int v = vb + (e & 1);
                if (u < 62 && v < 62) bufAt[u*62+v] = d[e];
            }
        }
    }
    __syncthreads();
    // P10: softmax over u per column v (4 lanes/col)
    {
        int v = lt>>2, g = lt&3;
        bool act = (v < 62);
        float m = -1e30f;
        if (act) for (int u=g; u<62; u+=4) m = fmaxf(m, bufAt[u*62+v]);
        m = fmaxf(m, __shfl_xor_sync(0xffffffffu, m, 1));
        m = fmaxf(m, __shfl_xor_sync(0xffffffffu, m, 2));
        float ssum = 0.f;
        if (act) for (int u=g; u<62; u+=4) { float e = __expf(bufAt[u*62+v]-m); bufAt[u*62+v]=e; ssum+=e; }
        ssum += __shfl_xor_sync(0xffffffffu, ssum, 1);
        ssum += __shfl_xor_sync(0xffffffffu, ssum, 2);
        float inv = __fdividef(1.0f, ssum);
        if (act) for (int u=g; u<62; u+=4) bufAt[u*62+v] *= inv;
    }
    __syncthreads();
    // P11: tmpS (reuse bufA, stride 62)
    const float* xm = sx + 310;
    {
        float a0=a_s[0],a1=a_s[1],a2=a_s[2],a3=a_s[3],a4=a_s[4];
        for (int i = lt; i < 3844; i += 256) {
            int ii = i/62, jj = i%62;
            const float* xi = xm + ii*5; const float* xj = xm + jj*5;
            float e = fabsf(xi[0]-xj[0])*a0 + fabsf(xi[1]-xj[1])*a1 + fabsf(xi[2]-xj[2])*a2
                    + fabsf(xi[3]-xj[3])*a3 + fabsf(xi[4]-xj[4])*a4;
            bufA[i] = __expf(fmaxf(e, 0.0f));
        }
    }
    __syncthreads();
    // P12: column reciprocal
    {
        int j = lt>>2, g = lt&3;
        bool act = (j < 62);
        float cs = 0.f;
        if (act) for (int i=g; i<62; i+=4) cs += bufA[i*62+j];
        cs += __shfl_xor_sync(0xffffffffu, cs, 1);
        cs += __shfl_xor_sync(0xffffffffu, cs, 2);
        if (act && g==0) colsum[j] = __fdividef(1.0f, cs);
    }
    __syncthreads();
    // P13: normalize + store S
    for (int i = lt; i < 3844; i += 256) {
        float s = bufA[i] * colsum[i%62];
        bufA[i] = s;
        out[S_BASE + (size_t)b*3844 + i] = s;
    }
    __syncthreads();
    // P14: Dg + d2
    {
        int j = lt>>2, g = lt&3;
        bool act = (j < 62);
        float cs = 0.f, dd = 0.f;
        if (act) {
            const float* xj = xm + j*5;
            for (int i=g; i<62; i+=4) {
                cs += bufA[i*62+j];
                const float* xi = xm + i*5;
                #pragma unroll
                for (int f=0; f<5; f++) { float d = xj[f]-xi[f]; dd += d*d; }
            }
        }
        cs += __shfl_xor_sync(0xffffffffu, cs, 1);
        cs += __shfl_xor_sync(0xffffffffu, cs, 2);
        dd += __shfl_xor_sync(0xffffffffu, dd, 1);
        dd += __shfl_xor_sync(0xffffffffu, dd, 2);
        if (act && g==0) { DgS_s[j] = cs; d2s_s[j] = dd; }
    }
    __syncthreads();
    // P15: Sloss partials
    {
        float sl = 0.f;
        for (int i = lt; i < 3844; i += 256) sl += bufA[i]*bufA[i];
        #pragma unroll
        for (int o=16; o; o>>=1) sl += __shfl_xor_sync(0xffffffffu, sl, o);
        if ((lt&31)==0) red_s[lt>>5] = sl;
    }
    __syncthreads();
    // P16: cheb accumulators -> g_acc [b][tv][16] + loss finalize
    if (lt < 186) {
        int t = lt/62, v = lt%62;
        float acc[15];
        #pragma unroll
        for (int k=0;k<15;k++) acc[k]=0.f;
        float dgm1 = DgS_s[v] - 1.0f;
        for (int u=0; u<62; u++) {
            float s  = bufA[u*62+v];
            float at = bufAt[u*62+v];
            float delta = (u==v) ? 1.0f : 0.0f;
            float lt_ = dgm1*delta - s;
            float c2 = 2.0f*lt_*lt_ - delta;
            float t0 = delta*at, t1 = lt_*at, t2 = c2*at;
            const float* xr = sx + t*310 + u*5;
            #pragma unroll
            for (int f=0; f<5; f++) {
                float xv = xr[f];
                acc[f]    += t0*xv;
                acc[5+f]  += t1*xv;
                acc[10+f] += t2*xv;
            }
        }
        float4* gp = reinterpret_cast<float4*>(g_acc + (size_t)b*2976 + (size_t)(t*62+v)*16);
        gp[0] = make_float4(acc[0],acc[1],acc[2],acc[3]);
        gp[1] = make_float4(acc[4],acc[5],acc[6],acc[7]);
        gp[2] = make_float4(acc[8],acc[9],acc[10],acc[11]);
        gp[3] = make_float4(acc[12],acc[13],acc[14],0.0f);
    } else if (lt == 192) {
        float sl = 0.f;
        #pragma unroll
        for (int w=0; w<8; w++) sl += red_s[w];
        atomicAdd(out + XR_ELEMS, sl * (ALPHA/(float)NBATCH));
        float dp = 0.f;
        for (int j=0; j<62; j++) dp += DgS_s[j]*d2s_s[j];
        atomicAdd(out + XR_ELEMS + 1, dp * ALPHA);
    }
}

// ============ K3: 4b -> mma.sync temporal conv -> LN (unchanged from R16) ============
__global__ void __launch_bounds__(512,4) stgcn_k3(
    const float* __restrict__ gx, const float* __restrict__ gTheta,
    const float* __restrict__ gtb, const float* __restrict__ grw,
    const float* __restrict__ grb, const float* __restrict__ ggamma,
    const float* __restrict__ gbeta, float* __restrict__ out)
{
    extern __shared__ float smarr[];
    const int tid = threadIdx.x;
    const int b = blockIdx.x;

    __nv_bfloat16* sgb = reinterpret_cast<__nv_bfloat16*>(smarr);  // [v<64][k<200] bf16
    float* zb    = smarr + 6400;
    float* Th_s  = zb   + 4032;
    float* x0_s  = Th_s + 960;
    float* tb_s  = x0_s + 320;
    float* rb_s  = tb_s + 64;
    float* rw_s  = rb_s + 64;
    float* gam_s = rw_s + 320;
    float* bet_s = gam_s+ 64;
    float* mu_s  = bet_s+ 64;
    float* iv_s  = mu_s + 64;

    for (int i = tid; i < 960; i += 512) Th_s[i] = gTheta[i];
    for (int i = tid; i < 310; i += 512) x0_s[i] = gx[(size_t)b*930 + i];
    for (int i = tid; i < 320; i += 512) rw_s[i] = grw[i];
    if (tid < 64) { tb_s[tid]=gtb[tid]; rb_s[tid]=grb[tid]; gam_s[tid]=ggamma[tid]; bet_s[tid]=gbeta[tid]; }
    __syncthreads();

    if (tid < 372) {
        int oh = (tid >= 186);
        int r = tid - oh*186;
        int t = r/62, v = r%62;
        int tv = t*62+v;
        const float4* ap4 = reinterpret_cast<const float4*>(g_acc + (size_t)b*2976 + (size_t)tv*16);
        float4 A0=__ldg(ap4), A1=__ldg(ap4+1), A2=__ldg(ap4+2), A3=__ldg(ap4+3);
        float a0[15] = {A0.x,A0.y,A0.z,A0.w, A1.x,A1.y,A1.z,A1.w,
                        A2.x,A2.y,A2.z,A2.w, A3.x,A3.y,A3.z};
        const float4* Th4 = reinterpret_cast<const float4*>(Th_s);
        int qb = oh*8;
        __nv_bfloat16* sgr = sgb + v*200 + t*64;
        #pragma unroll 2
        for (int q=0; q<8; q++) {
            int oq = qb+q;
            float zx=0.f, zy=0.f, zz=0.f, zw=0.f;
            #pragma unroll
            for (int kf=0; kf<15; kf++) {
                float4 th = Th4[kf*16+oq];
                float av = a0[kf];
                zx += av*th.x; zy += av*th.y; zz += av*th.z; zw += av*th.w;
            }
            int c0 = oq*4;
            __nv_bfloat162 p0; p0.x = __float2bfloat16(fmaxf(zx,0.f)); p0.y = __float2bfloat16(fmaxf(zy,0.f));
            __nv_bfloat162 p1; p1.x = __float2bfloat16(fmaxf(zz,0.f)); p1.y = __float2bfloat16(fmaxf(zw,0.f));
            *reinterpret_cast<__nv_bfloat162*>(sgr + c0)     = p0;
            *reinterpret_cast<__nv_bfloat162*>(sgr + c0 + 2) = p1;
        }
    }
    for (int i = tid; i < 384; i += 512) {
        int v = 62 + i/192, k = i%192;
        sgb[v*200 + k] = __float2bfloat16(0.0f);
    }
    __syncthreads();

    {
        int lane = tid & 31, w = tid >> 5;
        int m  = w & 3;
        int n0 = (w >> 2)*2, n1 = n0 + 1;
        int gr  = lane >> 2;
        int gc2 = (lane & 3)*2;
        float d0[4] = {0.f,0.f,0.f,0.f};
        float d1[4] = {0.f,0.f,0.f,0.f};
        const __nv_bfloat16* Abase = g_twb + (m*16 + gr)*192 + gc2;
        const __nv_bfloat16* B0 = sgb + (n0*8 + gr)*200 + gc2;
        const __nv_bfloat16* B1 = sgb + (n1*8 + gr)*200 + gc2;
        #pragma unroll
        for (int kt = 0; kt < 12; kt++) {
            int k0 = kt*16;
            unsigned a0 = *reinterpret_cast<const unsigned*>(Abase + k0);
            unsigned a1 = *reinterpret_cast<const unsigned*>(Abase + 8*192 + k0);
            unsigned a2 = *reinterpret_cast<const unsigned*>(Abase + k0 + 8);
            unsigned a3 = *reinterpret_cast<const unsigned*>(Abase + 8*192 + k0 + 8);
            unsigned b00 = *reinterpret_cast<const unsigned*>(B0 + k0);
            unsigned b01 = *reinterpret_cast<const unsigned*>(B0 + k0 + 8);
            unsigned b10 = *reinterpret_cast<const unsigned*>(B1 + k0);
            unsigned b11 = *reinterpret_cast<const unsigned*>(B1 + k0 + 8);
            mma_bf16(d0, a0, a1, a2, a3, b00, b01);
            mma_bf16(d1, a0, a1, a2, a3, b10, b11);
        }
        int oA = m*16 + gr, oB = oA + 8;
        #pragma unroll
        for (int ti = 0; ti < 2; ti++) {
            float* d = ti ? d1 : d0;
            int vbase = (ti ? n1 : n0)*8 + gc2;
            #pragma unroll
            for (int e = 0; e < 4; e++) {
                int o = (e >= 2) ? oB : oA;
                int v = vbase + (e & 1);
                if (v < 62) {
                    float tcv = (d[e] + tb_s[o]) * 0.25819889f;
                    const float* x0 = x0_s + v*5;
                    const float* rwp = rw_s + o*5;
                    float resv = rb_s[o] + x0[0]*rwp[0]+x0[1]*rwp[1]+x0[2]*rwp[2]
                               + x0[3]*rwp[3]+x0[4]*rwp[4];
                    zb[v*65+o] = fmaxf(resv + tcv, 0.0f);
                }
            }
        }
    }
    __syncthreads();

    {
        int v = tid>>3, g = tid&7;
        bool act = (v < 62);
        float s = 0.f;
        if (act) for (int o=g; o<64; o+=8) s += zb[v*65+o];
        #pragma unroll
        for (int o=4; o; o>>=1) s += __shfl_xor_sync(0xffffffffu, s, o);
        float mu = s * (1.0f/64.0f);
        float vv = 0.f;
        if (act) for (int o=g; o<64; o+=8) { float d = zb[v*65+o]-mu; vv += d*d; }
        #pragma unroll
        for (int o=4; o; o>>=1) vv += __shfl_xor_sync(0xffffffffu, vv, o);
        vv *= (1.0f/64.0f);
        if (act && g==0) { mu_s[v] = mu; iv_s[v] = rsqrtf(vv + LN_EPS); }
    }
    __syncthreads();
    for (int i = tid; i < 3968; i += 512) {
        int v = i>>6, o = i&63;
        float val = (zb[v*65+o]-mu_s[v])*iv_s[v]*gam_s[o] + bet_s[o];
        out[(size_t)b*3968 + i] = val;
    }
}

#define SMEM_A_BYTES (9344*4)
#define SMEM_K3_BYTES (12416*4)

extern "C" void kernel_launch(void* const* d_in, const int* in_sizes, int n_in,
                              void* d_out, int out_size) {
    const float* x     = (const float*)d_in[0];
    const float* U1    = (const float*)d_in[1];
    const float* U2    = (const float*)d_in[2];
    const float* U3    = (const float*)d_in[3];
    const float* be    = (const float*)d_in[4];
    const float* Ve    = (const float*)d_in[5];
    const float* W1    = (const float*)d_in[6];
    const float* W2    = (const float*)d_in[7];
    const float* W3    = (const float*)d_in[8];
    const float* bs    = (const float*)d_in[9];
    const float* Vs    = (const float*)d_in[10];
    const float* a     = (const float*)d_in[11];
    const float* Theta = (const float*)d_in[12];
    const float* tw    = (const float*)d_in[13];
    const float* tb    = (const float*)d_in[14];
    const float* rw    = (const float*)d_in[15];
    const float* rb    = (const float*)d_in[16];
    const float* gamma = (const float*)d_in[17];
    const float* beta  = (const float*)d_in[18];
    float* out = (float*)d_out;

    cudaFuncSetAttribute(stgcn_a,  cudaFuncAttributeMaxDynamicSharedMemorySize, SMEM_A_BYTES);
    cudaFuncSetAttribute(stgcn_k3, cudaFuncAttributeMaxDynamicSharedMemorySize, SMEM_K3_BYTES);

    prep_kernel<<<48, 256>>>(tw, Vs, out);
    stgcn_a<<<NBATCH, 256, SMEM_A_BYTES>>>(x, U1, U2, U3, be, Ve, W1, W2, W3,
                                           bs, a, out);
    stgcn_k3<<<NBATCH, 512, SMEM_K3_BYTES>>>(x, Theta, tb, rw, rb, gamma, beta, out);
}